// round 13
// baseline (speedup 1.0000x reference)
#include <cuda_runtime.h>
#include <cuda_fp16.h>
#include <math.h>
#include <stdint.h>

// Problem constants
constexpr int Bz = 8, Sq = 256, H = 768, Lr = 2, NE = 4, FF = 3072;
constexpr int NH = 12, HD = 64;
constexpr int T = Bz * Sq;
constexpr float EPS = 1e-5f;

// fp16 scratch
__device__ __half g_H1h[T * H];
__device__ __half g_Qh[T * H];
__device__ __half g_Kh[T * H];
__device__ __half g_Vh[T * H];
__device__ __half g_midh[(size_t)T * FF];
__device__ __half g_Wqh[Lr * H * H];
__device__ __half g_Wkh[Lr * H * H];
__device__ __half g_Wvh[Lr * H * H];
__device__ __half g_W1h[(size_t)Lr * NE * H * FF];
__device__ __half g_W2h[(size_t)Lr * NE * FF * H];
__device__ int   g_perm[T];
__device__ int   g_rank[T];
__device__ int   g_cnt[NE];
__device__ int   g_off[NE];

// GEMM smem geometry (bytes). Stage = BK=64 k-slice. Block tile 128x128, 3 stages.
// A: 128 rows x 64 halves (128B row), 16B-unit XOR swizzle u' = u ^ (r&7).
// B: 64 k-rows x 128 halves (256B row), swizzle u' = u ^ (k&7).
constexpr int ABUFB = 128 * 128;         // 16384
constexpr int BBUFB = 64 * 256;          // 16384
constexpr int STAGEB = ABUFB + BBUFB;    // 32768
constexpr int GEMM_SMEM = 3 * STAGEB;    // 98304

// ---------------------------------------------------------------- fp32 -> fp16 convert
__global__ void k_f2h(const float* __restrict__ in, __half* __restrict__ out, int n) {
    int i = (blockIdx.x * blockDim.x + threadIdx.x) * 4;
    if (i >= n) return;
    float4 v = *(const float4*)(in + i);
    *(__half2*)(out + i)     = __floats2half2_rn(v.x, v.y);
    *(__half2*)(out + i + 2) = __floats2half2_rn(v.z, v.w);
}

// ---------------------------------------------------------------- PE add
__global__ void k_add_pe(const float* __restrict__ xin, float* __restrict__ x) {
    int idx = blockIdx.x * blockDim.x + threadIdx.x;
    if (idx >= T * H) return;
    int d = idx % H;
    int s = (idx / H) % Sq;
    int i2 = d & ~1;
    float div = expf(-(float)i2 * (9.210340371976184f / (float)H));
    float ang = (float)s * div;
    float pe = (d & 1) ? cosf(ang) : sinf(ang);
    x[idx] = xin[idx] + pe;
}

// ---------------------------------------------------------------- routing
__global__ void k_route(const int* __restrict__ ntp) {
    __shared__ int scnt[NE];
    __shared__ int soff[NE];
    int tid = threadIdx.x;
    if (tid < NE) scnt[tid] = 0;
    __syncthreads();
    for (int t = tid; t < T; t += blockDim.x) {
        int e = ntp[t];
        g_rank[t] = atomicAdd(&scnt[e], 1);
    }
    __syncthreads();
    if (tid == 0) {
        int a = 0;
        for (int e = 0; e < NE; e++) {
            soff[e] = a; g_off[e] = a; g_cnt[e] = scnt[e]; a += scnt[e];
        }
    }
    __syncthreads();
    for (int t = tid; t < T; t += blockDim.x) {
        int e = ntp[t];
        g_perm[soff[e] + g_rank[t]] = t;
    }
}

// ---------------------------------------------------------------- layernorm (fp16 out)
__device__ __forceinline__ float block_sum_768(float v) {
    __shared__ float red[8];
    int tid = threadIdx.x;
    #pragma unroll
    for (int o = 16; o; o >>= 1) v += __shfl_xor_sync(0xffffffffu, v, o);
    if ((tid & 31) == 0) red[tid >> 5] = v;
    __syncthreads();
    float t = 0.f;
    if (tid < 32) {
        t = (tid < 8) ? red[tid] : 0.f;
        #pragma unroll
        for (int o = 4; o; o >>= 1) t += __shfl_xor_sync(0xffffffffu, t, o);
        if (tid == 0) red[0] = t;
    }
    __syncthreads();
    float r = red[0];
    __syncthreads();
    return r;
}

__global__ __launch_bounds__(256) void k_ln(const float* __restrict__ x,
                                            const float* __restrict__ w,
                                            const float* __restrict__ b) {
    int row = blockIdx.x;
    int tid = threadIdx.x;
    const float* xr = x + (size_t)row * H;
    float v0 = xr[tid], v1 = xr[tid + 256], v2 = xr[tid + 512];
    float mu = block_sum_768(v0 + v1 + v2) * (1.0f / H);
    float d0 = v0 - mu, d1 = v1 - mu, d2 = v2 - mu;
    float var = block_sum_768(d0 * d0 + d1 * d1 + d2 * d2) * (1.0f / H);
    float rstd = rsqrtf(var + EPS);
    __half* orow = g_H1h + (size_t)row * H;
    orow[tid]       = __float2half(d0 * rstd * w[tid]       + b[tid]);
    orow[tid + 256] = __float2half(d1 * rstd * w[tid + 256] + b[tid + 256]);
    orow[tid + 512] = __float2half(d2 * rstd * w[tid + 512] + b[tid + 512]);
}

// ---------------------------------------------------------------- mma / ldsm helpers
__device__ __forceinline__ uint32_t s2u(const void* p) {
    return (uint32_t)__cvta_generic_to_shared(p);
}

__device__ __forceinline__ void ldsm_x4(uint32_t (&r)[4], uint32_t addr) {
    asm volatile("ldmatrix.sync.aligned.m8n8.x4.shared.b16 {%0,%1,%2,%3}, [%4];"
        : "=r"(r[0]), "=r"(r[1]), "=r"(r[2]), "=r"(r[3]) : "r"(addr));
}

__device__ __forceinline__ void ldsm_x4_t(uint32_t (&r)[4], uint32_t addr) {
    asm volatile("ldmatrix.sync.aligned.m8n8.x4.trans.shared.b16 {%0,%1,%2,%3}, [%4];"
        : "=r"(r[0]), "=r"(r[1]), "=r"(r[2]), "=r"(r[3]) : "r"(addr));
}

__device__ __forceinline__ void mma_f16(float (&c)[4], const uint32_t (&a)[4], uint32_t b0, uint32_t b1) {
    asm volatile(
        "mma.sync.aligned.m16n8k16.row.col.f32.f16.f16.f32 "
        "{%0,%1,%2,%3},{%4,%5,%6,%7},{%8,%9},{%0,%1,%2,%3};"
        : "+f"(c[0]), "+f"(c[1]), "+f"(c[2]), "+f"(c[3])
        : "r"(a[0]), "r"(a[1]), "r"(a[2]), "r"(a[3]), "r"(b0), "r"(b1));
}

__device__ __forceinline__ void cp16(void* s, const void* g, int pred) {
    uint32_t sa = s2u(s);
    asm volatile(
        "{\n\t.reg .pred p;\n\t"
        "setp.ne.b32 p, %2, 0;\n\t"
        ".reg .b32 sz;\n\t"
        "selp.b32 sz, 16, 0, p;\n\t"
        "cp.async.ca.shared.global [%0], [%1], 16, sz;\n\t}"
        :: "r"(sa), "l"(g), "r"(pred));
}

// ---------------------------------------------------------------- fp16 GEMM core
// Block tile 128x128, 256 thr / 8 warps (4x2), warp tile 32x64, BK=64, 3-stage cp.async,
// ONE __syncthreads per k-iteration (trailing barrier proven redundant: loads target
// the buffer last read in compute(t-1), which all threads finished before this barrier).
__device__ __forceinline__ void gemm_mainloop_h(
    const __half* __restrict__ Arow, int avalid,
    const __half* __restrict__ Bg, int ldB, int Kdim, int n0,
    float (&c)[2][8][4], char* sm)
{
    int tid = threadIdx.x;
    int lane = tid & 31, warp = tid >> 5;
    int wm = (warp & 3) * 32, wn = (warp >> 2) * 64;

    int arow = tid >> 1;          // A: thread -> row tid>>1, u-chunks (tid&1)*4 .. +3
    int au0 = (tid & 1) * 4;
    int brow = tid >> 2;          // B: thread -> k-row tid>>2, u-chunks (tid&3)*4 .. +3
    int bu0 = (tid & 3) * 4;
    int ntile = Kdim / 64;

    auto load_stage = [&](int t, char* dst) {
        int kt = t * 64;
        char* As = dst;
        char* Bs = dst + ABUFB;
        const __half* ag = Arow + kt + au0 * 8;
        #pragma unroll
        for (int j = 0; j < 4; j++) {
            int u = au0 + j;
            cp16(As + arow * 128 + ((u ^ (arow & 7)) * 16), ag + j * 8, avalid);
        }
        const __half* bg = Bg + (size_t)(kt + brow) * ldB + n0 + bu0 * 8;
        #pragma unroll
        for (int j = 0; j < 4; j++) {
            int u = bu0 + j;
            cp16(Bs + brow * 256 + ((u ^ (brow & 7)) * 16), bg + j * 8, 1);
        }
    };

    load_stage(0, sm);
    asm volatile("cp.async.commit_group;");
    if (ntile > 1) load_stage(1, sm + STAGEB);
    asm volatile("cp.async.commit_group;");

    for (int t = 0; t < ntile; t++) {
        asm volatile("cp.async.wait_group 1;");
        __syncthreads();
        if (t + 2 < ntile) load_stage(t + 2, sm + ((t + 2) % 3) * STAGEB);
        asm volatile("cp.async.commit_group;");

        char* Ab = sm + (t % 3) * STAGEB;
        char* Bb = Ab + ABUFB;
        #pragma unroll
        for (int s16 = 0; s16 < 4; s16++) {
            uint32_t a[2][4];
            #pragma unroll
            for (int fm = 0; fm < 2; fm++) {
                int r = wm + fm * 16 + (lane & 15);
                int u = s16 * 2 + (lane >> 4);
                ldsm_x4(a[fm], s2u(Ab + r * 128 + ((u ^ (r & 7)) * 16)));
            }
            uint32_t b[8][2];
            #pragma unroll
            for (int fnp = 0; fnp < 4; fnp++) {
                int k = s16 * 16 + (lane & 7) + ((lane >> 3) & 1) * 8;
                int u = ((wn + fnp * 16) >> 3) + (lane >> 4);
                uint32_t r4[4];
                ldsm_x4_t(r4, s2u(Bb + k * 256 + ((u ^ (k & 7)) * 16)));
                b[2 * fnp][0] = r4[0]; b[2 * fnp][1] = r4[1];
                b[2 * fnp + 1][0] = r4[2]; b[2 * fnp + 1][1] = r4[3];
            }
            #pragma unroll
            for (int fm = 0; fm < 2; fm++)
                #pragma unroll
                for (int fn = 0; fn < 8; fn++)
                    mma_f16(c[fm][fn], a[fm], b[fn][0], b[fn][1]);
        }
    }
    asm volatile("cp.async.wait_group 0;");
}

// ---------------------------------------------------------------- QKV GEMM (fp16)
__global__ __launch_bounds__(256, 2) void k_qkv_tc(
    int l, const float* __restrict__ bq, const float* __restrict__ bk_, const float* __restrict__ bv)
{
    extern __shared__ char smbuf[];
    const __half* Bg; const float* bias; __half* C;
    if (blockIdx.z == 0)      { Bg = g_Wqh + (size_t)l * H * H; bias = bq;  C = g_Qh; }
    else if (blockIdx.z == 1) { Bg = g_Wkh + (size_t)l * H * H; bias = bk_; C = g_Kh; }
    else                      { Bg = g_Wvh + (size_t)l * H * H; bias = bv;  C = g_Vh; }
    int m0 = blockIdx.y * 128, n0 = blockIdx.x * 128;
    const __half* Arow = g_H1h + (size_t)(m0 + (threadIdx.x >> 1)) * H;
    float c[2][8][4] = {};
    gemm_mainloop_h(Arow, 1, Bg, H, H, n0, c, smbuf);

    int lane = threadIdx.x & 31, warp = threadIdx.x >> 5;
    int grp = lane >> 2, qid = lane & 3;
    int wm = (warp & 3) * 32, wn = (warp >> 2) * 64;
    #pragma unroll
    for (int fn = 0; fn < 8; fn++) {
        int col = n0 + wn + fn * 8 + qid * 2;
        float bx = bias[col], by = bias[col + 1];
        #pragma unroll
        for (int fm = 0; fm < 2; fm++) {
            int m = m0 + wm + fm * 16 + grp;
            *(__half2*)&C[(size_t)m * H + col]       = __floats2half2_rn(c[fm][fn][0] + bx, c[fm][fn][1] + by);
            *(__half2*)&C[(size_t)(m + 8) * H + col] = __floats2half2_rn(c[fm][fn][2] + bx, c[fm][fn][3] + by);
        }
    }
}

// ---------------------------------------------------------------- FFN GEMM1 (gather + gelu, fp16)
__device__ __forceinline__ float gelu_f(float v) {
    return 0.5f * v * (1.0f + erff(v * 0.70710678118654752f));
}

__global__ __launch_bounds__(256, 2) void k_ffn1_tc(int l, const float* __restrict__ b1l)
{
    extern __shared__ char smbuf[];
    int e = blockIdx.z;
    int cnt = g_cnt[e];
    int m0 = blockIdx.y * 128;
    if (m0 >= cnt) return;
    int off = g_off[e];
    int n0 = blockIdx.x * 128;
    const __half* Bg = g_W1h + ((size_t)l * NE + e) * H * FF;
    const float* bias = b1l + (size_t)e * FF;

    int s = m0 + (threadIdx.x >> 1);
    int valid = (s < cnt);
    const __half* Arow = g_H1h + (size_t)(valid ? g_perm[off + s] : 0) * H;
    float c[2][8][4] = {};
    gemm_mainloop_h(Arow, valid, Bg, FF, H, n0, c, smbuf);

    int lane = threadIdx.x & 31, warp = threadIdx.x >> 5;
    int grp = lane >> 2, qid = lane & 3;
    int wm = (warp & 3) * 32, wn = (warp >> 2) * 64;
    #pragma unroll
    for (int fn = 0; fn < 8; fn++) {
        int col = n0 + wn + fn * 8 + qid * 2;
        float bx = bias[col], by = bias[col + 1];
        #pragma unroll
        for (int fm = 0; fm < 2; fm++) {
            int gm = m0 + wm + fm * 16 + grp;
            if (gm < cnt) {
                size_t r = (size_t)(off + gm) * FF + col;
                *(__half2*)&g_midh[r] = __floats2half2_rn(gelu_f(c[fm][fn][0] + bx), gelu_f(c[fm][fn][1] + by));
            }
            if (gm + 8 < cnt) {
                size_t r = (size_t)(off + gm + 8) * FF + col;
                *(__half2*)&g_midh[r] = __floats2half2_rn(gelu_f(c[fm][fn][2] + bx), gelu_f(c[fm][fn][3] + by));
            }
        }
    }
}

// ---------------------------------------------------------------- FFN GEMM2 (split-K=2, residual scatter)
constexpr int KSPLIT = 2;
constexpr int KCHUNK = FF / KSPLIT;   // 1536

__global__ __launch_bounds__(256, 2) void k_ffn2_tc(int l, const float* __restrict__ b2l,
                                                    float* __restrict__ x)
{
    extern __shared__ char smbuf[];
    int e = blockIdx.z >> 1;
    int ks = blockIdx.z & 1;
    int cnt = g_cnt[e];
    int m0 = blockIdx.y * 128;
    if (m0 >= cnt) return;
    int off = g_off[e];
    int n0 = blockIdx.x * 128;
    int kbase = ks * KCHUNK;
    const __half* Bg = g_W2h + ((size_t)l * NE + e) * FF * H + (size_t)kbase * H;
    const float* bias = b2l + (size_t)e * H;

    int s = m0 + (threadIdx.x >> 1);
    int valid = (s < cnt);
    const __half* Arow = g_midh + (size_t)(off + (valid ? s : m0)) * FF + kbase;
    float c[2][8][4] = {};
    gemm_mainloop_h(Arow, valid, Bg, H, KCHUNK, n0, c, smbuf);

    int lane = threadIdx.x & 31, warp = threadIdx.x >> 5;
    int grp = lane >> 2, qid = lane & 3;
    int wm = (warp & 3) * 32, wn = (warp >> 2) * 64;

    int tok0[2], tok1[2];
    #pragma unroll
    for (int fm = 0; fm < 2; fm++) {
        int gm = m0 + wm + fm * 16 + grp;
        tok0[fm] = (gm < cnt)     ? g_perm[off + gm]     : -1;
        tok1[fm] = (gm + 8 < cnt) ? g_perm[off + gm + 8] : -1;
    }
    #pragma unroll
    for (int fn = 0; fn < 8; fn++) {
        int col = n0 + wn + fn * 8 + qid * 2;
        float bx = (ks == 0) ? bias[col]     : 0.f;
        float by = (ks == 0) ? bias[col + 1] : 0.f;
        #pragma unroll
        for (int fm = 0; fm < 2; fm++) {
            if (tok0[fm] >= 0) {
                float* p = &x[(size_t)tok0[fm] * H + col];
                atomicAdd(p,     c[fm][fn][0] + bx);
                atomicAdd(p + 1, c[fm][fn][1] + by);
            }
            if (tok1[fm] >= 0) {
                float* p = &x[(size_t)tok1[fm] * H + col];
                atomicAdd(p,     c[fm][fn][2] + bx);
                atomicAdd(p + 1, c[fm][fn][3] + by);
            }
        }
    }
}

// ---------------------------------------------------------------- attention (fp16 mma, unchanged)
constexpr int ATTN_SMEM = 73728;

__global__ __launch_bounds__(128, 2) void k_attn_tc(float* __restrict__ x) {
    extern __shared__ char smc[];
    char* Qsh = smc;
    char* Ksh = smc + 8192;
    char* Vsh = smc + 40960;
    char* Psh = smc;
    int qt = blockIdx.x, hd = blockIdx.y, b = blockIdx.z;
    int tid = threadIdx.x;
    int lane = tid & 31, warp = tid >> 5;
    int grp = lane >> 2, qid = lane & 3;
    int hoff = hd * HD;
    int m = warp * 16;

    for (int cc = tid; cc < 64 * 8; cc += 128) {
        int r = cc >> 3, u = cc & 7;
        cp16(Qsh + r * 128 + ((u ^ (r & 7)) * 16),
             g_Qh + (size_t)(b * Sq + qt * 64 + r) * H + hoff + u * 8, 1);
    }
    for (int cc = tid; cc < 256 * 8; cc += 128) {
        int r = cc >> 3, u = cc & 7;
        cp16(Ksh + r * 128 + ((u ^ (r & 7)) * 16),
             g_Kh + (size_t)(b * Sq + r) * H + hoff + u * 8, 1);
        cp16(Vsh + r * 128 + ((u ^ (r & 7)) * 16),
             g_Vh + (size_t)(b * Sq + r) * H + hoff + u * 8, 1);
    }
    asm volatile("cp.async.commit_group;");
    asm volatile("cp.async.wait_group 0;");
    __syncthreads();

    float c[32][4];
    #pragma unroll
    for (int fn = 0; fn < 32; fn++)
        #pragma unroll
        for (int j = 0; j < 4; j++) c[fn][j] = 0.f;

    #pragma unroll
    for (int s = 0; s < 4; s++) {
        uint32_t a[4];
        {
            int r = m + (lane & 15);
            ldsm_x4(a, s2u(Qsh + r * 128 + (((s * 2 + (lane >> 4)) ^ (r & 7)) * 16)));
        }
        #pragma unroll
        for (int nb = 0; nb < 16; nb++) {
            int r = nb * 16 + (lane & 15);
            uint32_t bb[4];
            ldsm_x4(bb, s2u(Ksh + r * 128 + (((s * 2 + (lane >> 4)) ^ (r & 7)) * 16)));
            mma_f16(c[2 * nb],     a, bb[0], bb[2]);
            mma_f16(c[2 * nb + 1], a, bb[1], bb[3]);
        }
    }
    __syncthreads();

    float mx0 = -1e30f, mx1 = -1e30f;
    #pragma unroll
    for (int fn = 0; fn < 32; fn++) {
        mx0 = fmaxf(mx0, fmaxf(c[fn][0], c[fn][1]));
        mx1 = fmaxf(mx1, fmaxf(c[fn][2], c[fn][3]));
    }
    #pragma unroll
    for (int o = 1; o <= 2; o <<= 1) {
        mx0 = fmaxf(mx0, __shfl_xor_sync(0xffffffffu, mx0, o));
        mx1 = fmaxf(mx1, __shfl_xor_sync(0xffffffffu, mx1, o));
    }
    float s0 = 0.f, s1 = 0.f;
    #pragma unroll
    for (int fn = 0; fn < 32; fn++) {
        c[fn][0] = __expf(c[fn][0] - mx0); s0 += c[fn][0];
        c[fn][1] = __expf(c[fn][1] - mx0); s0 += c[fn][1];
        c[fn][2] = __expf(c[fn][2] - mx1); s1 += c[fn][2];
        c[fn][3] = __expf(c[fn][3] - mx1); s1 += c[fn][3];
    }
    #pragma unroll
    for (int o = 1; o <= 2; o <<= 1) {
        s0 += __shfl_xor_sync(0xffffffffu, s0, o);
        s1 += __shfl_xor_sync(0xffffffffu, s1, o);
    }
    float inv0 = 1.f / s0, inv1 = 1.f / s1;
    #pragma unroll
    for (int fn = 0; fn < 32; fn++) {
        int r0 = m + grp, r1 = r0 + 8;
        int u0 = fn ^ (r0 & 7), u1 = fn ^ (r1 & 7);
        *(__half2*)(Psh + r0 * 512 + u0 * 16 + qid * 4) = __floats2half2_rn(c[fn][0] * inv0, c[fn][1] * inv0);
        *(__half2*)(Psh + r1 * 512 + u1 * 16 + qid * 4) = __floats2half2_rn(c[fn][2] * inv1, c[fn][3] * inv1);
    }
    __syncwarp();

    float c2[8][4];
    #pragma unroll
    for (int fn = 0; fn < 8; fn++)
        #pragma unroll
        for (int j = 0; j < 4; j++) c2[fn][j] = 0.f;

    #pragma unroll 4
    for (int s = 0; s < 16; s++) {
        uint32_t a[4];
        {
            int r = m + (lane & 15);
            int u = s * 2 + (lane >> 4);
            ldsm_x4(a, s2u(Psh + r * 512 + ((u ^ (r & 7)) * 16)));
        }
        #pragma unroll
        for (int nb = 0; nb < 4; nb++) {
            int k = s * 16 + (lane & 7) + ((lane >> 3) & 1) * 8;
            int u = nb * 2 + (lane >> 4);
            uint32_t r4[4];
            ldsm_x4_t(r4, s2u(Vsh + k * 128 + ((u ^ (k & 7)) * 16)));
            mma_f16(c2[2 * nb],     a, r4[0], r4[1]);
            mma_f16(c2[2 * nb + 1], a, r4[2], r4[3]);
        }
    }

    #pragma unroll
    for (int fn = 0; fn < 8; fn++) {
        int col = hoff + fn * 8 + qid * 2;
        size_t r0 = (size_t)(b * Sq + qt * 64 + m + grp) * H + col;
        size_t r1 = r0 + (size_t)8 * H;
        float2 v0 = *(float2*)&x[r0];
        v0.x += c2[fn][0]; v0.y += c2[fn][1];
        *(float2*)&x[r0] = v0;
        float2 v1 = *(float2*)&x[r1];
        v1.x += c2[fn][2]; v1.y += c2[fn][3];
        *(float2*)&x[r1] = v1;
    }
}

// ---------------------------------------------------------------- launch
extern "C" void kernel_launch(void* const* d_in, const int* in_sizes, int n_in,
                              void* d_out, int out_size) {
    (void)in_sizes; (void)n_in; (void)out_size;
    const float* x_in  = (const float*)d_in[0];
    const int*   ntp   = (const int*)d_in[2];
    const float* Wq    = (const float*)d_in[3];
    const float* bq    = (const float*)d_in[4];
    const float* Wk    = (const float*)d_in[5];
    const float* bk    = (const float*)d_in[6];
    const float* Wv    = (const float*)d_in[7];
    const float* bv    = (const float*)d_in[8];
    const float* ln1w  = (const float*)d_in[9];
    const float* ln1b  = (const float*)d_in[10];
    const float* ln2w  = (const float*)d_in[11];
    const float* ln2b  = (const float*)d_in[12];
    const float* W1    = (const float*)d_in[13];
    const float* b1    = (const float*)d_in[14];
    const float* W2    = (const float*)d_in[15];
    const float* b2    = (const float*)d_in[16];
    float* x = (float*)d_out;

    cudaFuncSetAttribute(k_attn_tc, cudaFuncAttributeMaxDynamicSharedMemorySize, ATTN_SMEM);
    cudaFuncSetAttribute(k_qkv_tc,  cudaFuncAttributeMaxDynamicSharedMemorySize, GEMM_SMEM);
    cudaFuncSetAttribute(k_ffn1_tc, cudaFuncAttributeMaxDynamicSharedMemorySize, GEMM_SMEM);
    cudaFuncSetAttribute(k_ffn2_tc, cudaFuncAttributeMaxDynamicSharedMemorySize, GEMM_SMEM);

    // weight conversion (fp32 -> fp16)
    {
        __half* dWq; cudaGetSymbolAddress((void**)&dWq, g_Wqh);
        __half* dWk; cudaGetSymbolAddress((void**)&dWk, g_Wkh);
        __half* dWv; cudaGetSymbolAddress((void**)&dWv, g_Wvh);
        __half* dW1; cudaGetSymbolAddress((void**)&dW1, g_W1h);
        __half* dW2; cudaGetSymbolAddress((void**)&dW2, g_W2h);
        int nqkv = Lr * H * H;
        int nff  = Lr * NE * H * FF;
        k_f2h<<<(nqkv / 4 + 255) / 256, 256>>>(Wq, dWq, nqkv);
        k_f2h<<<(nqkv / 4 + 255) / 256, 256>>>(Wk, dWk, nqkv);
        k_f2h<<<(nqkv / 4 + 255) / 256, 256>>>(Wv, dWv, nqkv);
        k_f2h<<<(nff / 4 + 255) / 256, 256>>>(W1, dW1, nff);
        k_f2h<<<(nff / 4 + 255) / 256, 256>>>(W2, dW2, nff);
    }

    k_add_pe<<<(T * H + 255) / 256, 256>>>(x_in, x);
    k_route<<<1, 256>>>(ntp);

    for (int l = 0; l < Lr; l++) {
        k_ln<<<T, 256>>>(x, ln1w + l * H, ln1b + l * H);
        k_qkv_tc<<<dim3(H / 128, T / 128, 3), 256, GEMM_SMEM>>>(
            l, bq + l * H, bk + l * H, bv + l * H);
        k_attn_tc<<<dim3(Sq / 64, NH, Bz), 128, ATTN_SMEM>>>(x);
        k_ln<<<T, 256>>>(x, ln2w + l * H, ln2b + l * H);
        k_ffn1_tc<<<dim3(FF / 128, T / 128, NE), 256, GEMM_SMEM>>>(
            l, b1 + (size_t)l * NE * FF);
        k_ffn2_tc<<<dim3(H / 128, T / 128, NE * KSPLIT), 256, GEMM_SMEM>>>(
            l, b2 + (size_t)l * NE * H, x);
    }
}

// round 15
// speedup vs baseline: 1.0962x; 1.0962x over previous
#include <cuda_runtime.h>
#include <cuda_fp16.h>
#include <math.h>
#include <stdint.h>

// Problem constants
constexpr int Bz = 8, Sq = 256, H = 768, Lr = 2, NE = 4, FF = 3072;
constexpr int NH = 12, HD = 64;
constexpr int T = Bz * Sq;
constexpr float EPS = 1e-5f;

// fp16 scratch
__device__ __half g_H1h[T * H];
__device__ __half g_Qh[T * H];
__device__ __half g_Kh[T * H];
__device__ __half g_Vh[T * H];
__device__ __half g_midh[(size_t)T * FF];
__device__ __half g_Wqh[Lr * H * H];
__device__ __half g_Wkh[Lr * H * H];
__device__ __half g_Wvh[Lr * H * H];
__device__ __half g_W1h[(size_t)Lr * NE * H * FF];
__device__ __half g_W2h[(size_t)Lr * NE * FF * H];
__device__ int   g_perm[T];
__device__ int   g_rank[T];
__device__ int   g_cnt[NE];
__device__ int   g_off[NE];

// GEMM smem geometry (bytes). Stage = BK=32 k-slice. Block tile 128x128, 4 stages.
// A: 128 rows x 32 halves (64B data), pitch 80B.
// B: 32 k-rows x 128 halves (256B row), 16B-unit XOR swizzle u' = u ^ (k&7).
constexpr int APITCHB = 80;
constexpr int ABUFB = 128 * APITCHB;     // 10240
constexpr int BBUFB = 32 * 256;          // 8192
constexpr int STAGEB = ABUFB + BBUFB;    // 18432
constexpr int NSTAGE = 4;
constexpr int GEMM_SMEM = NSTAGE * STAGEB;  // 73728

// ---------------------------------------------------------------- fp32 -> fp16 convert
__global__ void k_f2h(const float* __restrict__ in, __half* __restrict__ out, int n) {
    int i = (blockIdx.x * blockDim.x + threadIdx.x) * 4;
    if (i >= n) return;
    float4 v = *(const float4*)(in + i);
    *(__half2*)(out + i)     = __floats2half2_rn(v.x, v.y);
    *(__half2*)(out + i + 2) = __floats2half2_rn(v.z, v.w);
}

// ---------------------------------------------------------------- routing
__global__ void k_route(const int* __restrict__ ntp) {
    __shared__ int scnt[NE];
    __shared__ int soff[NE];
    int tid = threadIdx.x;
    if (tid < NE) scnt[tid] = 0;
    __syncthreads();
    for (int t = tid; t < T; t += blockDim.x) {
        int e = ntp[t];
        g_rank[t] = atomicAdd(&scnt[e], 1);
    }
    __syncthreads();
    if (tid == 0) {
        int a = 0;
        for (int e = 0; e < NE; e++) {
            soff[e] = a; g_off[e] = a; g_cnt[e] = scnt[e]; a += scnt[e];
        }
    }
    __syncthreads();
    for (int t = tid; t < T; t += blockDim.x) {
        int e = ntp[t];
        g_perm[soff[e] + g_rank[t]] = t;
    }
}

// ---------------------------------------------------------------- layernorm helpers
__device__ __forceinline__ float block_sum_768(float v) {
    __shared__ float red[8];
    int tid = threadIdx.x;
    #pragma unroll
    for (int o = 16; o; o >>= 1) v += __shfl_xor_sync(0xffffffffu, v, o);
    if ((tid & 31) == 0) red[tid >> 5] = v;
    __syncthreads();
    float t = 0.f;
    if (tid < 32) {
        t = (tid < 8) ? red[tid] : 0.f;
        #pragma unroll
        for (int o = 4; o; o >>= 1) t += __shfl_xor_sync(0xffffffffu, t, o);
        if (tid == 0) red[0] = t;
    }
    __syncthreads();
    float r = red[0];
    __syncthreads();
    return r;
}

// plain LN: x -> g_H1h
__global__ __launch_bounds__(256) void k_ln(const float* __restrict__ x,
                                            const float* __restrict__ w,
                                            const float* __restrict__ b) {
    int row = blockIdx.x;
    int tid = threadIdx.x;
    const float* xr = x + (size_t)row * H;
    float v0 = xr[tid], v1 = xr[tid + 256], v2 = xr[tid + 512];
    float mu = block_sum_768(v0 + v1 + v2) * (1.0f / H);
    float d0 = v0 - mu, d1 = v1 - mu, d2 = v2 - mu;
    float var = block_sum_768(d0 * d0 + d1 * d1 + d2 * d2) * (1.0f / H);
    float rstd = rsqrtf(var + EPS);
    __half* orow = g_H1h + (size_t)row * H;
    orow[tid]       = __float2half(d0 * rstd * w[tid]       + b[tid]);
    orow[tid + 256] = __float2half(d1 * rstd * w[tid + 256] + b[tid + 256]);
    orow[tid + 512] = __float2half(d2 * rstd * w[tid + 512] + b[tid + 512]);
}

// fused: x = x_in + PE; LN(x) -> g_H1h   (layer 0 entry)
__global__ __launch_bounds__(256) void k_pe_ln(const float* __restrict__ xin,
                                               float* __restrict__ x,
                                               const float* __restrict__ w,
                                               const float* __restrict__ b) {
    int row = blockIdx.x;
    int s = row % Sq;
    int tid = threadIdx.x;
    const float* xr = xin + (size_t)row * H;
    float v[3];
    #pragma unroll
    for (int p = 0; p < 3; p++) {
        int d = tid + p * 256;
        int i2 = d & ~1;
        float div = expf(-(float)i2 * (9.210340371976184f / (float)H));
        float ang = (float)s * div;
        float pe = (d & 1) ? cosf(ang) : sinf(ang);
        v[p] = xr[d] + pe;
        x[(size_t)row * H + d] = v[p];
    }
    float mu = block_sum_768(v[0] + v[1] + v[2]) * (1.0f / H);
    float d0 = v[0] - mu, d1 = v[1] - mu, d2 = v[2] - mu;
    float var = block_sum_768(d0 * d0 + d1 * d1 + d2 * d2) * (1.0f / H);
    float rstd = rsqrtf(var + EPS);
    __half* orow = g_H1h + (size_t)row * H;
    orow[tid]       = __float2half(d0 * rstd * w[tid]       + b[tid]);
    orow[tid + 256] = __float2half(d1 * rstd * w[tid + 256] + b[tid + 256]);
    orow[tid + 512] = __float2half(d2 * rstd * w[tid + 512] + b[tid + 512]);
}

// ---------------------------------------------------------------- mma / ldsm helpers
__device__ __forceinline__ uint32_t s2u(const void* p) {
    return (uint32_t)__cvta_generic_to_shared(p);
}

__device__ __forceinline__ void ldsm_x4(uint32_t (&r)[4], uint32_t addr) {
    asm volatile("ldmatrix.sync.aligned.m8n8.x4.shared.b16 {%0,%1,%2,%3}, [%4];"
        : "=r"(r[0]), "=r"(r[1]), "=r"(r[2]), "=r"(r[3]) : "r"(addr));
}

__device__ __forceinline__ void ldsm_x4_t(uint32_t (&r)[4], uint32_t addr) {
    asm volatile("ldmatrix.sync.aligned.m8n8.x4.trans.shared.b16 {%0,%1,%2,%3}, [%4];"
        : "=r"(r[0]), "=r"(r[1]), "=r"(r[2]), "=r"(r[3]) : "r"(addr));
}

__device__ __forceinline__ void mma_f16(float (&c)[4], const uint32_t (&a)[4], uint32_t b0, uint32_t b1) {
    asm volatile(
        "mma.sync.aligned.m16n8k16.row.col.f32.f16.f16.f32 "
        "{%0,%1,%2,%3},{%4,%5,%6,%7},{%8,%9},{%0,%1,%2,%3};"
        : "+f"(c[0]), "+f"(c[1]), "+f"(c[2]), "+f"(c[3])
        : "r"(a[0]), "r"(a[1]), "r"(a[2]), "r"(a[3]), "r"(b0), "r"(b1));
}

__device__ __forceinline__ void cp16(void* s, const void* g, int pred) {
    uint32_t sa = s2u(s);
    asm volatile(
        "{\n\t.reg .pred p;\n\t"
        "setp.ne.b32 p, %2, 0;\n\t"
        ".reg .b32 sz;\n\t"
        "selp.b32 sz, 16, 0, p;\n\t"
        "cp.async.ca.shared.global [%0], [%1], 16, sz;\n\t}"
        :: "r"(sa), "l"(g), "r"(pred));
}

// ---------------------------------------------------------------- fp16 GEMM core
// Block tile 128x128, 256 thr / 8 warps (4x2), warp tile 32x64, BK=32, 4-stage cp.async.
// (R11 structure: two barriers per k-iteration; only pipeline depth changed 3 -> 4.)
__device__ __forceinline__ void gemm_mainloop_h(
    const __half* __restrict__ Arow, int avalid,
    const __half* __restrict__ Bg, int ldB, int Kdim, int n0,
    float (&c)[2][8][4], char* sm)
{
    int tid = threadIdx.x;
    int lane = tid & 31, warp = tid >> 5;
    int wm = (warp & 3) * 32, wn = (warp >> 2) * 64;

    int arow = tid >> 1;
    int ah0 = (tid & 1) * 2;
    int ntile = Kdim / 32;

    auto load_stage = [&](int t, char* dst) {
        int kt = t * 32;
        char* As = dst;
        char* Bs = dst + ABUFB;
        const __half* ag = Arow + kt + ah0 * 8;
        cp16(As + arow * APITCHB + ah0 * 16,       ag,     avalid);
        cp16(As + arow * APITCHB + (ah0 + 1) * 16, ag + 8, avalid);
        #pragma unroll
        for (int j = 0; j < 2; j++) {
            int cc = tid * 2 + j;
            int k = cc >> 4, u = cc & 15;
            cp16(Bs + k * 256 + ((u ^ (k & 7)) * 16),
                 Bg + (size_t)(kt + k) * ldB + n0 + u * 8, 1);
        }
    };

    load_stage(0, sm);
    asm volatile("cp.async.commit_group;");
    if (ntile > 1) load_stage(1, sm + STAGEB);
    asm volatile("cp.async.commit_group;");
    if (ntile > 2) load_stage(2, sm + 2 * STAGEB);
    asm volatile("cp.async.commit_group;");

    for (int t = 0; t < ntile; t++) {
        asm volatile("cp.async.wait_group 2;");
        __syncthreads();
        if (t + 3 < ntile) load_stage(t + 3, sm + ((t + 3) % NSTAGE) * STAGEB);
        asm volatile("cp.async.commit_group;");

        char* Ab = sm + (t % NSTAGE) * STAGEB;
        char* Bb = Ab + ABUFB;
        #pragma unroll
        for (int s16 = 0; s16 < 2; s16++) {
            uint32_t a[2][4];
            #pragma unroll
            for (int fm = 0; fm < 2; fm++) {
                int r = wm + fm * 16 + (lane & 15);
                uint32_t addr = s2u(Ab + r * APITCHB + (s16 * 2 + (lane >> 4)) * 16);
                ldsm_x4(a[fm], addr);
            }
            uint32_t b[8][2];
            #pragma unroll
            for (int fnp = 0; fnp < 4; fnp++) {
                int k = s16 * 16 + (lane & 7) + ((lane >> 3) & 1) * 8;
                int u = ((wn + fnp * 16) >> 3) + (lane >> 4);
                uint32_t r4[4];
                ldsm_x4_t(r4, s2u(Bb + k * 256 + ((u ^ (k & 7)) * 16)));
                b[2 * fnp][0] = r4[0]; b[2 * fnp][1] = r4[1];
                b[2 * fnp + 1][0] = r4[2]; b[2 * fnp + 1][1] = r4[3];
            }
            #pragma unroll
            for (int fm = 0; fm < 2; fm++)
                #pragma unroll
                for (int fn = 0; fn < 8; fn++)
                    mma_f16(c[fm][fn], a[fm], b[fn][0], b[fn][1]);
        }
        __syncthreads();
    }
    asm volatile("cp.async.wait_group 0;");
}

// ---------------------------------------------------------------- QKV GEMM (fp16)
__global__ __launch_bounds__(256, 2) void k_qkv_tc(
    int l, const float* __restrict__ bq, const float* __restrict__ bk_, const float* __restrict__ bv)
{
    extern __shared__ char smbuf[];
    const __half* Bg; const float* bias; __half* C;
    if (blockIdx.z == 0)      { Bg = g_Wqh + (size_t)l * H * H; bias = bq;  C = g_Qh; }
    else if (blockIdx.z == 1) { Bg = g_Wkh + (size_t)l * H * H; bias = bk_; C = g_Kh; }
    else                      { Bg = g_Wvh + (size_t)l * H * H; bias = bv;  C = g_Vh; }
    int m0 = blockIdx.y * 128, n0 = blockIdx.x * 128;
    const __half* Arow = g_H1h + (size_t)(m0 + (threadIdx.x >> 1)) * H;
    float c[2][8][4] = {};
    gemm_mainloop_h(Arow, 1, Bg, H, H, n0, c, smbuf);

    int lane = threadIdx.x & 31, warp = threadIdx.x >> 5;
    int grp = lane >> 2, qid = lane & 3;
    int wm = (warp & 3) * 32, wn = (warp >> 2) * 64;
    #pragma unroll
    for (int fn = 0; fn < 8; fn++) {
        int col = n0 + wn + fn * 8 + qid * 2;
        float bx = bias[col], by = bias[col + 1];
        #pragma unroll
        for (int fm = 0; fm < 2; fm++) {
            int m = m0 + wm + fm * 16 + grp;
            *(__half2*)&C[(size_t)m * H + col]       = __floats2half2_rn(c[fm][fn][0] + bx, c[fm][fn][1] + by);
            *(__half2*)&C[(size_t)(m + 8) * H + col] = __floats2half2_rn(c[fm][fn][2] + bx, c[fm][fn][3] + by);
        }
    }
}

// ---------------------------------------------------------------- FFN GEMM1 (gather + gelu, fp16)
__device__ __forceinline__ float gelu_f(float v) {
    return 0.5f * v * (1.0f + erff(v * 0.70710678118654752f));
}

__global__ __launch_bounds__(256, 2) void k_ffn1_tc(int l, const float* __restrict__ b1l)
{
    extern __shared__ char smbuf[];
    int e = blockIdx.z;
    int cnt = g_cnt[e];
    int m0 = blockIdx.y * 128;
    if (m0 >= cnt) return;
    int off = g_off[e];
    int n0 = blockIdx.x * 128;
    const __half* Bg = g_W1h + ((size_t)l * NE + e) * H * FF;
    const float* bias = b1l + (size_t)e * FF;

    int s = m0 + (threadIdx.x >> 1);
    int valid = (s < cnt);
    const __half* Arow = g_H1h + (size_t)(valid ? g_perm[off + s] : 0) * H;
    float c[2][8][4] = {};
    gemm_mainloop_h(Arow, valid, Bg, FF, H, n0, c, smbuf);

    int lane = threadIdx.x & 31, warp = threadIdx.x >> 5;
    int grp = lane >> 2, qid = lane & 3;
    int wm = (warp & 3) * 32, wn = (warp >> 2) * 64;
    #pragma unroll
    for (int fn = 0; fn < 8; fn++) {
        int col = n0 + wn + fn * 8 + qid * 2;
        float bx = bias[col], by = bias[col + 1];
        #pragma unroll
        for (int fm = 0; fm < 2; fm++) {
            int gm = m0 + wm + fm * 16 + grp;
            if (gm < cnt) {
                size_t r = (size_t)(off + gm) * FF + col;
                *(__half2*)&g_midh[r] = __floats2half2_rn(gelu_f(c[fm][fn][0] + bx), gelu_f(c[fm][fn][1] + by));
            }
            if (gm + 8 < cnt) {
                size_t r = (size_t)(off + gm + 8) * FF + col;
                *(__half2*)&g_midh[r] = __floats2half2_rn(gelu_f(c[fm][fn][2] + bx), gelu_f(c[fm][fn][3] + by));
            }
        }
    }
}

// ---------------------------------------------------------------- FFN GEMM2 (split-K=2, residual scatter)
constexpr int KSPLIT = 2;
constexpr int KCHUNK = FF / KSPLIT;   // 1536

__global__ __launch_bounds__(256, 2) void k_ffn2_tc(int l, const float* __restrict__ b2l,
                                                    float* __restrict__ x)
{
    extern __shared__ char smbuf[];
    int e = blockIdx.z >> 1;
    int ks = blockIdx.z & 1;
    int cnt = g_cnt[e];
    int m0 = blockIdx.y * 128;
    if (m0 >= cnt) return;
    int off = g_off[e];
    int n0 = blockIdx.x * 128;
    int kbase = ks * KCHUNK;
    const __half* Bg = g_W2h + ((size_t)l * NE + e) * FF * H + (size_t)kbase * H;
    const float* bias = b2l + (size_t)e * H;

    int s = m0 + (threadIdx.x >> 1);
    int valid = (s < cnt);
    const __half* Arow = g_midh + (size_t)(off + (valid ? s : m0)) * FF + kbase;
    float c[2][8][4] = {};
    gemm_mainloop_h(Arow, valid, Bg, H, KCHUNK, n0, c, smbuf);

    int lane = threadIdx.x & 31, warp = threadIdx.x >> 5;
    int grp = lane >> 2, qid = lane & 3;
    int wm = (warp & 3) * 32, wn = (warp >> 2) * 64;

    int tok0[2], tok1[2];
    #pragma unroll
    for (int fm = 0; fm < 2; fm++) {
        int gm = m0 + wm + fm * 16 + grp;
        tok0[fm] = (gm < cnt)     ? g_perm[off + gm]     : -1;
        tok1[fm] = (gm + 8 < cnt) ? g_perm[off + gm + 8] : -1;
    }
    #pragma unroll
    for (int fn = 0; fn < 8; fn++) {
        int col = n0 + wn + fn * 8 + qid * 2;
        float bx = (ks == 0) ? bias[col]     : 0.f;
        float by = (ks == 0) ? bias[col + 1] : 0.f;
        #pragma unroll
        for (int fm = 0; fm < 2; fm++) {
            if (tok0[fm] >= 0) {
                float* p = &x[(size_t)tok0[fm] * H + col];
                atomicAdd(p,     c[fm][fn][0] + bx);
                atomicAdd(p + 1, c[fm][fn][1] + by);
            }
            if (tok1[fm] >= 0) {
                float* p = &x[(size_t)tok1[fm] * H + col];
                atomicAdd(p,     c[fm][fn][2] + bx);
                atomicAdd(p + 1, c[fm][fn][3] + by);
            }
        }
    }
}

// ---------------------------------------------------------------- attention (fp16 mma, unchanged)
constexpr int ATTN_SMEM = 73728;

__global__ __launch_bounds__(128, 2) void k_attn_tc(float* __restrict__ x) {
    extern __shared__ char smc[];
    char* Qsh = smc;
    char* Ksh = smc + 8192;
    char* Vsh = smc + 40960;
    char* Psh = smc;
    int qt = blockIdx.x, hd = blockIdx.y, b = blockIdx.z;
    int tid = threadIdx.x;
    int lane = tid & 31, warp = tid >> 5;
    int grp = lane >> 2, qid = lane & 3;
    int hoff = hd * HD;
    int m = warp * 16;

    for (int cc = tid; cc < 64 * 8; cc += 128) {
        int r = cc >> 3, u = cc & 7;
        cp16(Qsh + r * 128 + ((u ^ (r & 7)) * 16),
             g_Qh + (size_t)(b * Sq + qt * 64 + r) * H + hoff + u * 8, 1);
    }
    for (int cc = tid; cc < 256 * 8; cc += 128) {
        int r = cc >> 3, u = cc & 7;
        cp16(Ksh + r * 128 + ((u ^ (r & 7)) * 16),
             g_Kh + (size_t)(b * Sq + r) * H + hoff + u * 8, 1);
        cp16(Vsh + r * 128 + ((u ^ (r & 7)) * 16),
             g_Vh + (size_t)(b * Sq + r) * H + hoff + u * 8, 1);
    }
    asm volatile("cp.async.commit_group;");
    asm volatile("cp.async.wait_group 0;");
    __syncthreads();

    float c[32][4];
    #pragma unroll
    for (int fn = 0; fn < 32; fn++)
        #pragma unroll
        for (int j = 0; j < 4; j++) c[fn][j] = 0.f;

    #pragma unroll
    for (int s = 0; s < 4; s++) {
        uint32_t a[4];
        {
            int r = m + (lane & 15);
            ldsm_x4(a, s2u(Qsh + r * 128 + (((s * 2 + (lane >> 4)) ^ (r & 7)) * 16)));
        }
        #pragma unroll
        for (int nb = 0; nb < 16; nb++) {
            int r = nb * 16 + (lane & 15);
            uint32_t bb[4];
            ldsm_x4(bb, s2u(Ksh + r * 128 + (((s * 2 + (lane >> 4)) ^ (r & 7)) * 16)));
            mma_f16(c[2 * nb],     a, bb[0], bb[2]);
            mma_f16(c[2 * nb + 1], a, bb[1], bb[3]);
        }
    }
    __syncthreads();

    float mx0 = -1e30f, mx1 = -1e30f;
    #pragma unroll
    for (int fn = 0; fn < 32; fn++) {
        mx0 = fmaxf(mx0, fmaxf(c[fn][0], c[fn][1]));
        mx1 = fmaxf(mx1, fmaxf(c[fn][2], c[fn][3]));
    }
    #pragma unroll
    for (int o = 1; o <= 2; o <<= 1) {
        mx0 = fmaxf(mx0, __shfl_xor_sync(0xffffffffu, mx0, o));
        mx1 = fmaxf(mx1, __shfl_xor_sync(0xffffffffu, mx1, o));
    }
    float s0 = 0.f, s1 = 0.f;
    #pragma unroll
    for (int fn = 0; fn < 32; fn++) {
        c[fn][0] = __expf(c[fn][0] - mx0); s0 += c[fn][0];
        c[fn][1] = __expf(c[fn][1] - mx0); s0 += c[fn][1];
        c[fn][2] = __expf(c[fn][2] - mx1); s1 += c[fn][2];
        c[fn][3] = __expf(c[fn][3] - mx1); s1 += c[fn][3];
    }
    #pragma unroll
    for (int o = 1; o <= 2; o <<= 1) {
        s0 += __shfl_xor_sync(0xffffffffu, s0, o);
        s1 += __shfl_xor_sync(0xffffffffu, s1, o);
    }
    float inv0 = 1.f / s0, inv1 = 1.f / s1;
    #pragma unroll
    for (int fn = 0; fn < 32; fn++) {
        int r0 = m + grp, r1 = r0 + 8;
        int u0 = fn ^ (r0 & 7), u1 = fn ^ (r1 & 7);
        *(__half2*)(Psh + r0 * 512 + u0 * 16 + qid * 4) = __floats2half2_rn(c[fn][0] * inv0, c[fn][1] * inv0);
        *(__half2*)(Psh + r1 * 512 + u1 * 16 + qid * 4) = __floats2half2_rn(c[fn][2] * inv1, c[fn][3] * inv1);
    }
    __syncwarp();

    float c2[8][4];
    #pragma unroll
    for (int fn = 0; fn < 8; fn++)
        #pragma unroll
        for (int j = 0; j < 4; j++) c2[fn][j] = 0.f;

    #pragma unroll 4
    for (int s = 0; s < 16; s++) {
        uint32_t a[4];
        {
            int r = m + (lane & 15);
            int u = s * 2 + (lane >> 4);
            ldsm_x4(a, s2u(Psh + r * 512 + ((u ^ (r & 7)) * 16)));
        }
        #pragma unroll
        for (int nb = 0; nb < 4; nb++) {
            int k = s * 16 + (lane & 7) + ((lane >> 3) & 1) * 8;
            int u = nb * 2 + (lane >> 4);
            uint32_t r4[4];
            ldsm_x4_t(r4, s2u(Vsh + k * 128 + ((u ^ (k & 7)) * 16)));
            mma_f16(c2[2 * nb],     a, r4[0], r4[1]);
            mma_f16(c2[2 * nb + 1], a, r4[2], r4[3]);
        }
    }

    #pragma unroll
    for (int fn = 0; fn < 8; fn++) {
        int col = hoff + fn * 8 + qid * 2;
        size_t r0 = (size_t)(b * Sq + qt * 64 + m + grp) * H + col;
        size_t r1 = r0 + (size_t)8 * H;
        float2 v0 = *(float2*)&x[r0];
        v0.x += c2[fn][0]; v0.y += c2[fn][1];
        *(float2*)&x[r0] = v0;
        float2 v1 = *(float2*)&x[r1];
        v1.x += c2[fn][2]; v1.y += c2[fn][3];
        *(float2*)&x[r1] = v1;
    }
}

// ---------------------------------------------------------------- launch
extern "C" void kernel_launch(void* const* d_in, const int* in_sizes, int n_in,
                              void* d_out, int out_size) {
    (void)in_sizes; (void)n_in; (void)out_size;
    const float* x_in  = (const float*)d_in[0];
    const int*   ntp   = (const int*)d_in[2];
    const float* Wq    = (const float*)d_in[3];
    const float* bq    = (const float*)d_in[4];
    const float* Wk    = (const float*)d_in[5];
    const float* bk    = (const float*)d_in[6];
    const float* Wv    = (const float*)d_in[7];
    const float* bv    = (const float*)d_in[8];
    const float* ln1w  = (const float*)d_in[9];
    const float* ln1b  = (const float*)d_in[10];
    const float* ln2w  = (const float*)d_in[11];
    const float* ln2b  = (const float*)d_in[12];
    const float* W1    = (const float*)d_in[13];
    const float* b1    = (const float*)d_in[14];
    const float* W2    = (const float*)d_in[15];
    const float* b2    = (const float*)d_in[16];
    float* x = (float*)d_out;

    cudaFuncSetAttribute(k_attn_tc, cudaFuncAttributeMaxDynamicSharedMemorySize, ATTN_SMEM);
    cudaFuncSetAttribute(k_qkv_tc,  cudaFuncAttributeMaxDynamicSharedMemorySize, GEMM_SMEM);
    cudaFuncSetAttribute(k_ffn1_tc, cudaFuncAttributeMaxDynamicSharedMemorySize, GEMM_SMEM);
    cudaFuncSetAttribute(k_ffn2_tc, cudaFuncAttributeMaxDynamicSharedMemorySize, GEMM_SMEM);

    __half* dWq; cudaGetSymbolAddress((void**)&dWq, g_Wqh);
    __half* dWk; cudaGetSymbolAddress((void**)&dWk, g_Wkh);
    __half* dWv; cudaGetSymbolAddress((void**)&dWv, g_Wvh);
    __half* dW1; cudaGetSymbolAddress((void**)&dW1, g_W1h);
    __half* dW2; cudaGetSymbolAddress((void**)&dW2, g_W2h);
    int nqkv = Lr * H * H;
    int nff  = Lr * NE * H * FF;

    // Launch order tuned so ncu (-s 5 -c 1) captures k_qkv_tc as the 6th launch.
    k_f2h<<<(nqkv / 4 + 255) / 256, 256>>>(Wq, dWq, nqkv);       // 0
    k_f2h<<<(nqkv / 4 + 255) / 256, 256>>>(Wk, dWk, nqkv);       // 1
    k_f2h<<<(nqkv / 4 + 255) / 256, 256>>>(Wv, dWv, nqkv);       // 2
    k_route<<<1, 256>>>(ntp);                                     // 3
    k_pe_ln<<<T, 256>>>(x_in, x, ln1w, ln1b);                     // 4 (PE + LN1 layer0 fused)
    k_qkv_tc<<<dim3(H / 128, T / 128, 3), 256, GEMM_SMEM>>>(      // 5  <- profiled
        0, bq, bk, bv);

    // FFN weight conversion (needed before ffn1 of layer 0)
    k_f2h<<<(nff / 4 + 255) / 256, 256>>>(W1, dW1, nff);
    k_f2h<<<(nff / 4 + 255) / 256, 256>>>(W2, dW2, nff);

    k_attn_tc<<<dim3(Sq / 64, NH, Bz), 128, ATTN_SMEM>>>(x);
    k_ln<<<T, 256>>>(x, ln2w, ln2b);
    k_ffn1_tc<<<dim3(FF / 128, T / 128, NE), 256, GEMM_SMEM>>>(0, b1);
    k_ffn2_tc<<<dim3(H / 128, T / 128, NE * KSPLIT), 256, GEMM_SMEM>>>(0, b2, x);

    // layer 1
    k_ln<<<T, 256>>>(x, ln1w + H, ln1b + H);
    k_qkv_tc<<<dim3(H / 128, T / 128, 3), 256, GEMM_SMEM>>>(
        1, bq + H, bk + H, bv + H);
    k_attn_tc<<<dim3(Sq / 64, NH, Bz), 128, ATTN_SMEM>>>(x);
    k_ln<<<T, 256>>>(x, ln2w + H, ln2b + H);
    k_ffn1_tc<<<dim3(FF / 128, T / 128, NE), 256, GEMM_SMEM>>>(1, b1 + (size_t)NE * FF);
    k_ffn2_tc<<<dim3(H / 128, T / 128, NE * KSPLIT), 256, GEMM_SMEM>>>(1, b2 + (size_t)NE * H, x);
}

// round 16
// speedup vs baseline: 1.1127x; 1.0150x over previous
#include <cuda_runtime.h>
#include <cuda_fp16.h>
#include <math.h>
#include <stdint.h>

// Problem constants
constexpr int Bz = 8, Sq = 256, H = 768, Lr = 2, NE = 4, FF = 3072;
constexpr int NH = 12, HD = 64;
constexpr int T = Bz * Sq;
constexpr float EPS = 1e-5f;

// fp16 scratch
__device__ __half g_H1h[T * H];
__device__ __half g_Qh[T * H];
__device__ __half g_Kh[T * H];
__device__ __half g_Vh[T * H];
__device__ __half g_midh[(size_t)T * FF];
__device__ __half g_Wqh[Lr * H * H];
__device__ __half g_Wkh[Lr * H * H];
__device__ __half g_Wvh[Lr * H * H];
__device__ __half g_W1h[(size_t)Lr * NE * H * FF];
__device__ __half g_W2h[(size_t)Lr * NE * FF * H];
__device__ int   g_perm[T];
__device__ int   g_rank[T];
__device__ int   g_cnt[NE];
__device__ int   g_off[NE];

// GEMM smem geometry (bytes). Stage = BK=32 k-slice. Block tile 128x128, 3 stages (R11 config).
constexpr int APITCHB = 80;
constexpr int ABUFB = 128 * APITCHB;     // 10240
constexpr int BBUFB = 32 * 256;          // 8192
constexpr int STAGEB = ABUFB + BBUFB;    // 18432
constexpr int GEMM_SMEM = 3 * STAGEB;    // 55296

// ---------------------------------------------------------------- fp32 -> fp16 convert
__global__ void k_f2h(const float* __restrict__ in, __half* __restrict__ out, int n) {
    int i = (blockIdx.x * blockDim.x + threadIdx.x) * 4;
    if (i >= n) return;
    float4 v = *(const float4*)(in + i);
    *(__half2*)(out + i)     = __floats2half2_rn(v.x, v.y);
    *(__half2*)(out + i + 2) = __floats2half2_rn(v.z, v.w);
}

// ---------------------------------------------------------------- routing (1024 threads)
__global__ __launch_bounds__(1024) void k_route(const int* __restrict__ ntp) {
    __shared__ int scnt[NE];
    __shared__ int soff[NE];
    int tid = threadIdx.x;
    if (tid < NE) scnt[tid] = 0;
    __syncthreads();
    for (int t = tid; t < T; t += 1024) {
        int e = ntp[t];
        g_rank[t] = atomicAdd(&scnt[e], 1);
    }
    __syncthreads();
    if (tid == 0) {
        int a = 0;
        for (int e = 0; e < NE; e++) {
            soff[e] = a; g_off[e] = a; g_cnt[e] = scnt[e]; a += scnt[e];
        }
    }
    __syncthreads();
    for (int t = tid; t < T; t += 1024) {
        int e = ntp[t];
        g_perm[soff[e] + g_rank[t]] = t;
    }
}

// ---------------------------------------------------------------- layernorm helpers
__device__ __forceinline__ float block_sum_768(float v) {
    __shared__ float red[8];
    int tid = threadIdx.x;
    #pragma unroll
    for (int o = 16; o; o >>= 1) v += __shfl_xor_sync(0xffffffffu, v, o);
    if ((tid & 31) == 0) red[tid >> 5] = v;
    __syncthreads();
    float t = 0.f;
    if (tid < 32) {
        t = (tid < 8) ? red[tid] : 0.f;
        #pragma unroll
        for (int o = 4; o; o >>= 1) t += __shfl_xor_sync(0xffffffffu, t, o);
        if (tid == 0) red[0] = t;
    }
    __syncthreads();
    float r = red[0];
    __syncthreads();
    return r;
}

// plain LN: x -> g_H1h
__global__ __launch_bounds__(256) void k_ln(const float* __restrict__ x,
                                            const float* __restrict__ w,
                                            const float* __restrict__ b) {
    int row = blockIdx.x;
    int tid = threadIdx.x;
    const float* xr = x + (size_t)row * H;
    float v0 = xr[tid], v1 = xr[tid + 256], v2 = xr[tid + 512];
    float mu = block_sum_768(v0 + v1 + v2) * (1.0f / H);
    float d0 = v0 - mu, d1 = v1 - mu, d2 = v2 - mu;
    float var = block_sum_768(d0 * d0 + d1 * d1 + d2 * d2) * (1.0f / H);
    float rstd = rsqrtf(var + EPS);
    __half* orow = g_H1h + (size_t)row * H;
    orow[tid]       = __float2half(d0 * rstd * w[tid]       + b[tid]);
    orow[tid + 256] = __float2half(d1 * rstd * w[tid + 256] + b[tid + 256]);
    orow[tid + 512] = __float2half(d2 * rstd * w[tid + 512] + b[tid + 512]);
}

// fused: x = x_in + PE; LN(x) -> g_H1h   (layer 0 entry)
__global__ __launch_bounds__(256) void k_pe_ln(const float* __restrict__ xin,
                                               float* __restrict__ x,
                                               const float* __restrict__ w,
                                               const float* __restrict__ b) {
    int row = blockIdx.x;
    int s = row % Sq;
    int tid = threadIdx.x;
    const float* xr = xin + (size_t)row * H;
    float v[3];
    #pragma unroll
    for (int p = 0; p < 3; p++) {
        int d = tid + p * 256;
        int i2 = d & ~1;
        float div = expf(-(float)i2 * (9.210340371976184f / (float)H));
        float ang = (float)s * div;
        float pe = (d & 1) ? cosf(ang) : sinf(ang);
        v[p] = xr[d] + pe;
        x[(size_t)row * H + d] = v[p];
    }
    float mu = block_sum_768(v[0] + v[1] + v[2]) * (1.0f / H);
    float d0 = v[0] - mu, d1 = v[1] - mu, d2 = v[2] - mu;
    float var = block_sum_768(d0 * d0 + d1 * d1 + d2 * d2) * (1.0f / H);
    float rstd = rsqrtf(var + EPS);
    __half* orow = g_H1h + (size_t)row * H;
    orow[tid]       = __float2half(d0 * rstd * w[tid]       + b[tid]);
    orow[tid + 256] = __float2half(d1 * rstd * w[tid + 256] + b[tid + 256]);
    orow[tid + 512] = __float2half(d2 * rstd * w[tid + 512] + b[tid + 512]);
}

// ---------------------------------------------------------------- mma / ldsm helpers
__device__ __forceinline__ uint32_t s2u(const void* p) {
    return (uint32_t)__cvta_generic_to_shared(p);
}

__device__ __forceinline__ void ldsm_x4(uint32_t (&r)[4], uint32_t addr) {
    asm volatile("ldmatrix.sync.aligned.m8n8.x4.shared.b16 {%0,%1,%2,%3}, [%4];"
        : "=r"(r[0]), "=r"(r[1]), "=r"(r[2]), "=r"(r[3]) : "r"(addr));
}

__device__ __forceinline__ void ldsm_x4_t(uint32_t (&r)[4], uint32_t addr) {
    asm volatile("ldmatrix.sync.aligned.m8n8.x4.trans.shared.b16 {%0,%1,%2,%3}, [%4];"
        : "=r"(r[0]), "=r"(r[1]), "=r"(r[2]), "=r"(r[3]) : "r"(addr));
}

__device__ __forceinline__ void mma_f16(float (&c)[4], const uint32_t (&a)[4], uint32_t b0, uint32_t b1) {
    asm volatile(
        "mma.sync.aligned.m16n8k16.row.col.f32.f16.f16.f32 "
        "{%0,%1,%2,%3},{%4,%5,%6,%7},{%8,%9},{%0,%1,%2,%3};"
        : "+f"(c[0]), "+f"(c[1]), "+f"(c[2]), "+f"(c[3])
        : "r"(a[0]), "r"(a[1]), "r"(a[2]), "r"(a[3]), "r"(b0), "r"(b1));
}

__device__ __forceinline__ void cp16(void* s, const void* g, int pred) {
    uint32_t sa = s2u(s);
    asm volatile(
        "{\n\t.reg .pred p;\n\t"
        "setp.ne.b32 p, %2, 0;\n\t"
        ".reg .b32 sz;\n\t"
        "selp.b32 sz, 16, 0, p;\n\t"
        "cp.async.ca.shared.global [%0], [%1], 16, sz;\n\t}"
        :: "r"(sa), "l"(g), "r"(pred));
}

// ---------------------------------------------------------------- fp16 GEMM core
// R11-proven config: block tile 128x128, 8 warps (4x2), warp tile 32x64, BK=32,
// 3-stage cp.async, two __syncthreads per k-iteration.
__device__ __forceinline__ void gemm_mainloop_h(
    const __half* __restrict__ Arow, int avalid,
    const __half* __restrict__ Bg, int ldB, int Kdim, int n0,
    float (&c)[2][8][4], char* sm)
{
    int tid = threadIdx.x;
    int lane = tid & 31, warp = tid >> 5;
    int wm = (warp & 3) * 32, wn = (warp >> 2) * 64;

    int arow = tid >> 1;
    int ah0 = (tid & 1) * 2;
    int ntile = Kdim / 32;

    auto load_stage = [&](int t, char* dst) {
        int kt = t * 32;
        char* As = dst;
        char* Bs = dst + ABUFB;
        const __half* ag = Arow + kt + ah0 * 8;
        cp16(As + arow * APITCHB + ah0 * 16,       ag,     avalid);
        cp16(As + arow * APITCHB + (ah0 + 1) * 16, ag + 8, avalid);
        #pragma unroll
        for (int j = 0; j < 2; j++) {
            int cc = tid * 2 + j;
            int k = cc >> 4, u = cc & 15;
            cp16(Bs + k * 256 + ((u ^ (k & 7)) * 16),
                 Bg + (size_t)(kt + k) * ldB + n0 + u * 8, 1);
        }
    };

    load_stage(0, sm);
    asm volatile("cp.async.commit_group;");
    if (ntile > 1) load_stage(1, sm + STAGEB);
    asm volatile("cp.async.commit_group;");

    for (int t = 0; t < ntile; t++) {
        asm volatile("cp.async.wait_group 1;");
        __syncthreads();
        if (t + 2 < ntile) load_stage(t + 2, sm + ((t + 2) % 3) * STAGEB);
        asm volatile("cp.async.commit_group;");

        char* Ab = sm + (t % 3) * STAGEB;
        char* Bb = Ab + ABUFB;
        #pragma unroll
        for (int s16 = 0; s16 < 2; s16++) {
            uint32_t a[2][4];
            #pragma unroll
            for (int fm = 0; fm < 2; fm++) {
                int r = wm + fm * 16 + (lane & 15);
                uint32_t addr = s2u(Ab + r * APITCHB + (s16 * 2 + (lane >> 4)) * 16);
                ldsm_x4(a[fm], addr);
            }
            uint32_t b[8][2];
            #pragma unroll
            for (int fnp = 0; fnp < 4; fnp++) {
                int k = s16 * 16 + (lane & 7) + ((lane >> 3) & 1) * 8;
                int u = ((wn + fnp * 16) >> 3) + (lane >> 4);
                uint32_t r4[4];
                ldsm_x4_t(r4, s2u(Bb + k * 256 + ((u ^ (k & 7)) * 16)));
                b[2 * fnp][0] = r4[0]; b[2 * fnp][1] = r4[1];
                b[2 * fnp + 1][0] = r4[2]; b[2 * fnp + 1][1] = r4[3];
            }
            #pragma unroll
            for (int fm = 0; fm < 2; fm++)
                #pragma unroll
                for (int fn = 0; fn < 8; fn++)
                    mma_f16(c[fm][fn], a[fm], b[fn][0], b[fn][1]);
        }
        __syncthreads();
    }
    asm volatile("cp.async.wait_group 0;");
}

// ---------------------------------------------------------------- QKV GEMM (fp16)
__global__ __launch_bounds__(256, 2) void k_qkv_tc(
    int l, const float* __restrict__ bq, const float* __restrict__ bk_, const float* __restrict__ bv)
{
    extern __shared__ char smbuf[];
    const __half* Bg; const float* bias; __half* C;
    if (blockIdx.z == 0)      { Bg = g_Wqh + (size_t)l * H * H; bias = bq;  C = g_Qh; }
    else if (blockIdx.z == 1) { Bg = g_Wkh + (size_t)l * H * H; bias = bk_; C = g_Kh; }
    else                      { Bg = g_Wvh + (size_t)l * H * H; bias = bv;  C = g_Vh; }
    int m0 = blockIdx.y * 128, n0 = blockIdx.x * 128;
    const __half* Arow = g_H1h + (size_t)(m0 + (threadIdx.x >> 1)) * H;
    float c[2][8][4] = {};
    gemm_mainloop_h(Arow, 1, Bg, H, H, n0, c, smbuf);

    int lane = threadIdx.x & 31, warp = threadIdx.x >> 5;
    int grp = lane >> 2, qid = lane & 3;
    int wm = (warp & 3) * 32, wn = (warp >> 2) * 64;
    #pragma unroll
    for (int fn = 0; fn < 8; fn++) {
        int col = n0 + wn + fn * 8 + qid * 2;
        float bx = bias[col], by = bias[col + 1];
        #pragma unroll
        for (int fm = 0; fm < 2; fm++) {
            int m = m0 + wm + fm * 16 + grp;
            *(__half2*)&C[(size_t)m * H + col]       = __floats2half2_rn(c[fm][fn][0] + bx, c[fm][fn][1] + by);
            *(__half2*)&C[(size_t)(m + 8) * H + col] = __floats2half2_rn(c[fm][fn][2] + bx, c[fm][fn][3] + by);
        }
    }
}

// ---------------------------------------------------------------- FFN GEMM1 (gather + gelu, fp16)
__device__ __forceinline__ float gelu_f(float v) {
    return 0.5f * v * (1.0f + erff(v * 0.70710678118654752f));
}

__global__ __launch_bounds__(256, 2) void k_ffn1_tc(int l, const float* __restrict__ b1l)
{
    extern __shared__ char smbuf[];
    int e = blockIdx.z;
    int cnt = g_cnt[e];
    int m0 = blockIdx.y * 128;
    if (m0 >= cnt) return;
    int off = g_off[e];
    int n0 = blockIdx.x * 128;
    const __half* Bg = g_W1h + ((size_t)l * NE + e) * H * FF;
    const float* bias = b1l + (size_t)e * FF;

    int s = m0 + (threadIdx.x >> 1);
    int valid = (s < cnt);
    const __half* Arow = g_H1h + (size_t)(valid ? g_perm[off + s] : 0) * H;
    float c[2][8][4] = {};
    gemm_mainloop_h(Arow, valid, Bg, FF, H, n0, c, smbuf);

    int lane = threadIdx.x & 31, warp = threadIdx.x >> 5;
    int grp = lane >> 2, qid = lane & 3;
    int wm = (warp & 3) * 32, wn = (warp >> 2) * 64;
    #pragma unroll
    for (int fn = 0; fn < 8; fn++) {
        int col = n0 + wn + fn * 8 + qid * 2;
        float bx = bias[col], by = bias[col + 1];
        #pragma unroll
        for (int fm = 0; fm < 2; fm++) {
            int gm = m0 + wm + fm * 16 + grp;
            if (gm < cnt) {
                size_t r = (size_t)(off + gm) * FF + col;
                *(__half2*)&g_midh[r] = __floats2half2_rn(gelu_f(c[fm][fn][0] + bx), gelu_f(c[fm][fn][1] + by));
            }
            if (gm + 8 < cnt) {
                size_t r = (size_t)(off + gm + 8) * FF + col;
                *(__half2*)&g_midh[r] = __floats2half2_rn(gelu_f(c[fm][fn][2] + bx), gelu_f(c[fm][fn][3] + by));
            }
        }
    }
}

// ---------------------------------------------------------------- FFN GEMM2 (split-K=2, residual scatter)
constexpr int KSPLIT = 2;
constexpr int KCHUNK = FF / KSPLIT;   // 1536

__global__ __launch_bounds__(256, 2) void k_ffn2_tc(int l, const float* __restrict__ b2l,
                                                    float* __restrict__ x)
{
    extern __shared__ char smbuf[];
    int e = blockIdx.z >> 1;
    int ks = blockIdx.z & 1;
    int cnt = g_cnt[e];
    int m0 = blockIdx.y * 128;
    if (m0 >= cnt) return;
    int off = g_off[e];
    int n0 = blockIdx.x * 128;
    int kbase = ks * KCHUNK;
    const __half* Bg = g_W2h + ((size_t)l * NE + e) * FF * H + (size_t)kbase * H;
    const float* bias = b2l + (size_t)e * H;

    int s = m0 + (threadIdx.x >> 1);
    int valid = (s < cnt);
    const __half* Arow = g_midh + (size_t)(off + (valid ? s : m0)) * FF + kbase;
    float c[2][8][4] = {};
    gemm_mainloop_h(Arow, valid, Bg, H, KCHUNK, n0, c, smbuf);

    int lane = threadIdx.x & 31, warp = threadIdx.x >> 5;
    int grp = lane >> 2, qid = lane & 3;
    int wm = (warp & 3) * 32, wn = (warp >> 2) * 64;

    int tok0[2], tok1[2];
    #pragma unroll
    for (int fm = 0; fm < 2; fm++) {
        int gm = m0 + wm + fm * 16 + grp;
        tok0[fm] = (gm < cnt)     ? g_perm[off + gm]     : -1;
        tok1[fm] = (gm + 8 < cnt) ? g_perm[off + gm + 8] : -1;
    }
    #pragma unroll
    for (int fn = 0; fn < 8; fn++) {
        int col = n0 + wn + fn * 8 + qid * 2;
        float bx = (ks == 0) ? bias[col]     : 0.f;
        float by = (ks == 0) ? bias[col + 1] : 0.f;
        #pragma unroll
        for (int fm = 0; fm < 2; fm++) {
            if (tok0[fm] >= 0) {
                float* p = &x[(size_t)tok0[fm] * H + col];
                atomicAdd(p,     c[fm][fn][0] + bx);
                atomicAdd(p + 1, c[fm][fn][1] + by);
            }
            if (tok1[fm] >= 0) {
                float* p = &x[(size_t)tok1[fm] * H + col];
                atomicAdd(p,     c[fm][fn][2] + bx);
                atomicAdd(p + 1, c[fm][fn][3] + by);
            }
        }
    }
}

// ---------------------------------------------------------------- attention (fp16 mma, unchanged)
constexpr int ATTN_SMEM = 73728;

__global__ __launch_bounds__(128, 2) void k_attn_tc(float* __restrict__ x) {
    extern __shared__ char smc[];
    char* Qsh = smc;
    char* Ksh = smc + 8192;
    char* Vsh = smc + 40960;
    char* Psh = smc;
    int qt = blockIdx.x, hd = blockIdx.y, b = blockIdx.z;
    int tid = threadIdx.x;
    int lane = tid & 31, warp = tid >> 5;
    int grp = lane >> 2, qid = lane & 3;
    int hoff = hd * HD;
    int m = warp * 16;

    for (int cc = tid; cc < 64 * 8; cc += 128) {
        int r = cc >> 3, u = cc & 7;
        cp16(Qsh + r * 128 + ((u ^ (r & 7)) * 16),
             g_Qh + (size_t)(b * Sq + qt * 64 + r) * H + hoff + u * 8, 1);
    }
    for (int cc = tid; cc < 256 * 8; cc += 128) {
        int r = cc >> 3, u = cc & 7;
        cp16(Ksh + r * 128 + ((u ^ (r & 7)) * 16),
             g_Kh + (size_t)(b * Sq + r) * H + hoff + u * 8, 1);
        cp16(Vsh + r * 128 + ((u ^ (r & 7)) * 16),
             g_Vh + (size_t)(b * Sq + r) * H + hoff + u * 8, 1);
    }
    asm volatile("cp.async.commit_group;");
    asm volatile("cp.async.wait_group 0;");
    __syncthreads();

    float c[32][4];
    #pragma unroll
    for (int fn = 0; fn < 32; fn++)
        #pragma unroll
        for (int j = 0; j < 4; j++) c[fn][j] = 0.f;

    #pragma unroll
    for (int s = 0; s < 4; s++) {
        uint32_t a[4];
        {
            int r = m + (lane & 15);
            ldsm_x4(a, s2u(Qsh + r * 128 + (((s * 2 + (lane >> 4)) ^ (r & 7)) * 16)));
        }
        #pragma unroll
        for (int nb = 0; nb < 16; nb++) {
            int r = nb * 16 + (lane & 15);
            uint32_t bb[4];
            ldsm_x4(bb, s2u(Ksh + r * 128 + (((s * 2 + (lane >> 4)) ^ (r & 7)) * 16)));
            mma_f16(c[2 * nb],     a, bb[0], bb[2]);
            mma_f16(c[2 * nb + 1], a, bb[1], bb[3]);
        }
    }
    __syncthreads();

    float mx0 = -1e30f, mx1 = -1e30f;
    #pragma unroll
    for (int fn = 0; fn < 32; fn++) {
        mx0 = fmaxf(mx0, fmaxf(c[fn][0], c[fn][1]));
        mx1 = fmaxf(mx1, fmaxf(c[fn][2], c[fn][3]));
    }
    #pragma unroll
    for (int o = 1; o <= 2; o <<= 1) {
        mx0 = fmaxf(mx0, __shfl_xor_sync(0xffffffffu, mx0, o));
        mx1 = fmaxf(mx1, __shfl_xor_sync(0xffffffffu, mx1, o));
    }
    float s0 = 0.f, s1 = 0.f;
    #pragma unroll
    for (int fn = 0; fn < 32; fn++) {
        c[fn][0] = __expf(c[fn][0] - mx0); s0 += c[fn][0];
        c[fn][1] = __expf(c[fn][1] - mx0); s0 += c[fn][1];
        c[fn][2] = __expf(c[fn][2] - mx1); s1 += c[fn][2];
        c[fn][3] = __expf(c[fn][3] - mx1); s1 += c[fn][3];
    }
    #pragma unroll
    for (int o = 1; o <= 2; o <<= 1) {
        s0 += __shfl_xor_sync(0xffffffffu, s0, o);
        s1 += __shfl_xor_sync(0xffffffffu, s1, o);
    }
    float inv0 = 1.f / s0, inv1 = 1.f / s1;
    #pragma unroll
    for (int fn = 0; fn < 32; fn++) {
        int r0 = m + grp, r1 = r0 + 8;
        int u0 = fn ^ (r0 & 7), u1 = fn ^ (r1 & 7);
        *(__half2*)(Psh + r0 * 512 + u0 * 16 + qid * 4) = __floats2half2_rn(c[fn][0] * inv0, c[fn][1] * inv0);
        *(__half2*)(Psh + r1 * 512 + u1 * 16 + qid * 4) = __floats2half2_rn(c[fn][2] * inv1, c[fn][3] * inv1);
    }
    __syncwarp();

    float c2[8][4];
    #pragma unroll
    for (int fn = 0; fn < 8; fn++)
        #pragma unroll
        for (int j = 0; j < 4; j++) c2[fn][j] = 0.f;

    #pragma unroll 4
    for (int s = 0; s < 16; s++) {
        uint32_t a[4];
        {
            int r = m + (lane & 15);
            int u = s * 2 + (lane >> 4);
            ldsm_x4(a, s2u(Psh + r * 512 + ((u ^ (r & 7)) * 16)));
        }
        #pragma unroll
        for (int nb = 0; nb < 4; nb++) {
            int k = s * 16 + (lane & 7) + ((lane >> 3) & 1) * 8;
            int u = nb * 2 + (lane >> 4);
            uint32_t r4[4];
            ldsm_x4_t(r4, s2u(Vsh + k * 128 + ((u ^ (k & 7)) * 16)));
            mma_f16(c2[2 * nb],     a, r4[0], r4[1]);
            mma_f16(c2[2 * nb + 1], a, r4[2], r4[3]);
        }
    }

    #pragma unroll
    for (int fn = 0; fn < 8; fn++) {
        int col = hoff + fn * 8 + qid * 2;
        size_t r0 = (size_t)(b * Sq + qt * 64 + m + grp) * H + col;
        size_t r1 = r0 + (size_t)8 * H;
        float2 v0 = *(float2*)&x[r0];
        v0.x += c2[fn][0]; v0.y += c2[fn][1];
        *(float2*)&x[r0] = v0;
        float2 v1 = *(float2*)&x[r1];
        v1.x += c2[fn][2]; v1.y += c2[fn][3];
        *(float2*)&x[r1] = v1;
    }
}

// ---------------------------------------------------------------- launch
extern "C" void kernel_launch(void* const* d_in, const int* in_sizes, int n_in,
                              void* d_out, int out_size) {
    (void)in_sizes; (void)n_in; (void)out_size;
    const float* x_in  = (const float*)d_in[0];
    const int*   ntp   = (const int*)d_in[2];
    const float* Wq    = (const float*)d_in[3];
    const float* bq    = (const float*)d_in[4];
    const float* Wk    = (const float*)d_in[5];
    const float* bk    = (const float*)d_in[6];
    const float* Wv    = (const float*)d_in[7];
    const float* bv    = (const float*)d_in[8];
    const float* ln1w  = (const float*)d_in[9];
    const float* ln1b  = (const float*)d_in[10];
    const float* ln2w  = (const float*)d_in[11];
    const float* ln2b  = (const float*)d_in[12];
    const float* W1    = (const float*)d_in[13];
    const float* b1    = (const float*)d_in[14];
    const float* W2    = (const float*)d_in[15];
    const float* b2    = (const float*)d_in[16];
    float* x = (float*)d_out;

    cudaFuncSetAttribute(k_attn_tc, cudaFuncAttributeMaxDynamicSharedMemorySize, ATTN_SMEM);
    cudaFuncSetAttribute(k_qkv_tc,  cudaFuncAttributeMaxDynamicSharedMemorySize, GEMM_SMEM);
    cudaFuncSetAttribute(k_ffn1_tc, cudaFuncAttributeMaxDynamicSharedMemorySize, GEMM_SMEM);
    cudaFuncSetAttribute(k_ffn2_tc, cudaFuncAttributeMaxDynamicSharedMemorySize, GEMM_SMEM);

    __half* dWq; cudaGetSymbolAddress((void**)&dWq, g_Wqh);
    __half* dWk; cudaGetSymbolAddress((void**)&dWk, g_Wkh);
    __half* dWv; cudaGetSymbolAddress((void**)&dWv, g_Wvh);
    __half* dW1; cudaGetSymbolAddress((void**)&dW1, g_W1h);
    __half* dW2; cudaGetSymbolAddress((void**)&dW2, g_W2h);
    int nqkv = Lr * H * H;
    int nff  = Lr * NE * H * FF;

    k_f2h<<<(nqkv / 4 + 255) / 256, 256>>>(Wq, dWq, nqkv);       // 0
    k_f2h<<<(nqkv / 4 + 255) / 256, 256>>>(Wk, dWk, nqkv);       // 1
    k_f2h<<<(nqkv / 4 + 255) / 256, 256>>>(Wv, dWv, nqkv);       // 2
    k_route<<<1, 1024>>>(ntp);                                    // 3
    k_pe_ln<<<T, 256>>>(x_in, x, ln1w, ln1b);                     // 4
    k_qkv_tc<<<dim3(H / 128, T / 128, 3), 256, GEMM_SMEM>>>(      // 5
        0, bq, bk, bv);

    k_f2h<<<(nff / 4 + 255) / 256, 256>>>(W1, dW1, nff);
    k_f2h<<<(nff / 4 + 255) / 256, 256>>>(W2, dW2, nff);

    k_attn_tc<<<dim3(Sq / 64, NH, Bz), 128, ATTN_SMEM>>>(x);
    k_ln<<<T, 256>>>(x, ln2w, ln2b);
    k_ffn1_tc<<<dim3(FF / 128, T / 128, NE), 256, GEMM_SMEM>>>(0, b1);
    k_ffn2_tc<<<dim3(H / 128, T / 128, NE * KSPLIT), 256, GEMM_SMEM>>>(0, b2, x);

    // layer 1
    k_ln<<<T, 256>>>(x, ln1w + H, ln1b + H);
    k_qkv_tc<<<dim3(H / 128, T / 128, 3), 256, GEMM_SMEM>>>(
        1, bq + H, bk + H, bv + H);
    k_attn_tc<<<dim3(Sq / 64, NH, Bz), 128, ATTN_SMEM>>>(x);
    k_ln<<<T, 256>>>(x, ln2w + H, ln2b + H);
    k_ffn1_tc<<<dim3(FF / 128, T / 128, NE), 256, GEMM_SMEM>>>(1, b1 + (size_t)NE * FF);
    k_ffn2_tc<<<dim3(H / 128, T / 128, NE * KSPLIT), 256, GEMM_SMEM>>>(1, b2 + (size_t)NE * H, x);
}

// round 17
// speedup vs baseline: 1.1254x; 1.0115x over previous
#include <cuda_runtime.h>
#include <cuda_fp16.h>
#include <math.h>
#include <stdint.h>

// Problem constants
constexpr int Bz = 8, Sq = 256, H = 768, Lr = 2, NE = 4, FF = 3072;
constexpr int NH = 12, HD = 64;
constexpr int T = Bz * Sq;
constexpr float EPS = 1e-5f;

// fp16 scratch
__device__ __half g_H1h[T * H];
__device__ __half g_Qh[T * H];
__device__ __half g_Kh[T * H];
__device__ __half g_Vh[T * H];
__device__ __half g_midh[(size_t)T * FF];
__device__ __half g_Wqh[Lr * H * H];
__device__ __half g_Wkh[Lr * H * H];
__device__ __half g_Wvh[Lr * H * H];
__device__ __half g_W1h[(size_t)Lr * NE * H * FF];
__device__ __half g_W2h[(size_t)Lr * NE * FF * H];
__device__ int   g_perm[T];
__device__ int   g_rank[T];
__device__ int   g_cnt[NE];
__device__ int   g_off[NE];

// GEMM smem geometry (bytes). Stage = BK=32 k-slice. Block tile 128x128, 3 stages (R11 config).
constexpr int APITCHB = 80;
constexpr int ABUFB = 128 * APITCHB;     // 10240
constexpr int BBUFB = 32 * 256;          // 8192
constexpr int STAGEB = ABUFB + BBUFB;    // 18432
constexpr int GEMM_SMEM = 3 * STAGEB;    // 55296

// ---------------------------------------------------------------- fp32 -> fp16 convert
__global__ void k_f2h(const float* __restrict__ in, __half* __restrict__ out, int n) {
    int i = (blockIdx.x * blockDim.x + threadIdx.x) * 4;
    if (i >= n) return;
    float4 v = *(const float4*)(in + i);
    *(__half2*)(out + i)     = __floats2half2_rn(v.x, v.y);
    *(__half2*)(out + i + 2) = __floats2half2_rn(v.z, v.w);
}

// ---------------------------------------------------------------- routing (1024 threads)
__global__ __launch_bounds__(1024) void k_route(const int* __restrict__ ntp) {
    __shared__ int scnt[NE];
    __shared__ int soff[NE];
    int tid = threadIdx.x;
    if (tid < NE) scnt[tid] = 0;
    __syncthreads();
    for (int t = tid; t < T; t += 1024) {
        int e = ntp[t];
        g_rank[t] = atomicAdd(&scnt[e], 1);
    }
    __syncthreads();
    if (tid == 0) {
        int a = 0;
        for (int e = 0; e < NE; e++) {
            soff[e] = a; g_off[e] = a; g_cnt[e] = scnt[e]; a += scnt[e];
        }
    }
    __syncthreads();
    for (int t = tid; t < T; t += 1024) {
        int e = ntp[t];
        g_perm[soff[e] + g_rank[t]] = t;
    }
}

// ---------------------------------------------------------------- layernorm helpers
__device__ __forceinline__ float block_sum_768(float v) {
    __shared__ float red[8];
    int tid = threadIdx.x;
    #pragma unroll
    for (int o = 16; o; o >>= 1) v += __shfl_xor_sync(0xffffffffu, v, o);
    if ((tid & 31) == 0) red[tid >> 5] = v;
    __syncthreads();
    float t = 0.f;
    if (tid < 32) {
        t = (tid < 8) ? red[tid] : 0.f;
        #pragma unroll
        for (int o = 4; o; o >>= 1) t += __shfl_xor_sync(0xffffffffu, t, o);
        if (tid == 0) red[0] = t;
    }
    __syncthreads();
    float r = red[0];
    __syncthreads();
    return r;
}

// plain LN: x -> g_H1h
__global__ __launch_bounds__(256) void k_ln(const float* __restrict__ x,
                                            const float* __restrict__ w,
                                            const float* __restrict__ b) {
    int row = blockIdx.x;
    int tid = threadIdx.x;
    const float* xr = x + (size_t)row * H;
    float v0 = xr[tid], v1 = xr[tid + 256], v2 = xr[tid + 512];
    float mu = block_sum_768(v0 + v1 + v2) * (1.0f / H);
    float d0 = v0 - mu, d1 = v1 - mu, d2 = v2 - mu;
    float var = block_sum_768(d0 * d0 + d1 * d1 + d2 * d2) * (1.0f / H);
    float rstd = rsqrtf(var + EPS);
    __half* orow = g_H1h + (size_t)row * H;
    orow[tid]       = __float2half(d0 * rstd * w[tid]       + b[tid]);
    orow[tid + 256] = __float2half(d1 * rstd * w[tid + 256] + b[tid + 256]);
    orow[tid + 512] = __float2half(d2 * rstd * w[tid + 512] + b[tid + 512]);
}

// fused: x = x_in + PE; LN(x) -> g_H1h   (layer 0 entry)
__global__ __launch_bounds__(256) void k_pe_ln(const float* __restrict__ xin,
                                               float* __restrict__ x,
                                               const float* __restrict__ w,
                                               const float* __restrict__ b) {
    int row = blockIdx.x;
    int s = row % Sq;
    int tid = threadIdx.x;
    const float* xr = xin + (size_t)row * H;
    float v[3];
    #pragma unroll
    for (int p = 0; p < 3; p++) {
        int d = tid + p * 256;
        int i2 = d & ~1;
        float div = expf(-(float)i2 * (9.210340371976184f / (float)H));
        float ang = (float)s * div;
        float pe = (d & 1) ? cosf(ang) : sinf(ang);
        v[p] = xr[d] + pe;
        x[(size_t)row * H + d] = v[p];
    }
    float mu = block_sum_768(v[0] + v[1] + v[2]) * (1.0f / H);
    float d0 = v[0] - mu, d1 = v[1] - mu, d2 = v[2] - mu;
    float var = block_sum_768(d0 * d0 + d1 * d1 + d2 * d2) * (1.0f / H);
    float rstd = rsqrtf(var + EPS);
    __half* orow = g_H1h + (size_t)row * H;
    orow[tid]       = __float2half(d0 * rstd * w[tid]       + b[tid]);
    orow[tid + 256] = __float2half(d1 * rstd * w[tid + 256] + b[tid + 256]);
    orow[tid + 512] = __float2half(d2 * rstd * w[tid + 512] + b[tid + 512]);
}

// ---------------------------------------------------------------- mma / ldsm helpers
__device__ __forceinline__ uint32_t s2u(const void* p) {
    return (uint32_t)__cvta_generic_to_shared(p);
}

__device__ __forceinline__ void ldsm_x4(uint32_t (&r)[4], uint32_t addr) {
    asm volatile("ldmatrix.sync.aligned.m8n8.x4.shared.b16 {%0,%1,%2,%3}, [%4];"
        : "=r"(r[0]), "=r"(r[1]), "=r"(r[2]), "=r"(r[3]) : "r"(addr));
}

__device__ __forceinline__ void ldsm_x4_t(uint32_t (&r)[4], uint32_t addr) {
    asm volatile("ldmatrix.sync.aligned.m8n8.x4.trans.shared.b16 {%0,%1,%2,%3}, [%4];"
        : "=r"(r[0]), "=r"(r[1]), "=r"(r[2]), "=r"(r[3]) : "r"(addr));
}

__device__ __forceinline__ void mma_f16(float (&c)[4], const uint32_t (&a)[4], uint32_t b0, uint32_t b1) {
    asm volatile(
        "mma.sync.aligned.m16n8k16.row.col.f32.f16.f16.f32 "
        "{%0,%1,%2,%3},{%4,%5,%6,%7},{%8,%9},{%0,%1,%2,%3};"
        : "+f"(c[0]), "+f"(c[1]), "+f"(c[2]), "+f"(c[3])
        : "r"(a[0]), "r"(a[1]), "r"(a[2]), "r"(a[3]), "r"(b0), "r"(b1));
}

__device__ __forceinline__ void cp16(void* s, const void* g, int pred) {
    uint32_t sa = s2u(s);
    asm volatile(
        "{\n\t.reg .pred p;\n\t"
        "setp.ne.b32 p, %2, 0;\n\t"
        ".reg .b32 sz;\n\t"
        "selp.b32 sz, 16, 0, p;\n\t"
        "cp.async.ca.shared.global [%0], [%1], 16, sz;\n\t}"
        :: "r"(sa), "l"(g), "r"(pred));
}

// ---------------------------------------------------------------- fp16 GEMM core
// R11 config (block tile 128x128, 8 warps 4x2, warp tile 32x64, BK=32, 3-stage)
// with SINGLE __syncthreads per k-iteration. Safety: at the top barrier of iter t,
// every thread has completed compute(t-1); load_stage(t+2) overwrites the buffer
// whose last reader was compute(t-1) -> no race.
__device__ __forceinline__ void gemm_mainloop_h(
    const __half* __restrict__ Arow, int avalid,
    const __half* __restrict__ Bg, int ldB, int Kdim, int n0,
    float (&c)[2][8][4], char* sm)
{
    int tid = threadIdx.x;
    int lane = tid & 31, warp = tid >> 5;
    int wm = (warp & 3) * 32, wn = (warp >> 2) * 64;

    int arow = tid >> 1;
    int ah0 = (tid & 1) * 2;
    int ntile = Kdim / 32;

    auto load_stage = [&](int t, char* dst) {
        int kt = t * 32;
        char* As = dst;
        char* Bs = dst + ABUFB;
        const __half* ag = Arow + kt + ah0 * 8;
        cp16(As + arow * APITCHB + ah0 * 16,       ag,     avalid);
        cp16(As + arow * APITCHB + (ah0 + 1) * 16, ag + 8, avalid);
        #pragma unroll
        for (int j = 0; j < 2; j++) {
            int cc = tid * 2 + j;
            int k = cc >> 4, u = cc & 15;
            cp16(Bs + k * 256 + ((u ^ (k & 7)) * 16),
                 Bg + (size_t)(kt + k) * ldB + n0 + u * 8, 1);
        }
    };

    load_stage(0, sm);
    asm volatile("cp.async.commit_group;");
    if (ntile > 1) load_stage(1, sm + STAGEB);
    asm volatile("cp.async.commit_group;");

    for (int t = 0; t < ntile; t++) {
        asm volatile("cp.async.wait_group 1;");
        __syncthreads();
        if (t + 2 < ntile) load_stage(t + 2, sm + ((t + 2) % 3) * STAGEB);
        asm volatile("cp.async.commit_group;");

        char* Ab = sm + (t % 3) * STAGEB;
        char* Bb = Ab + ABUFB;
        #pragma unroll
        for (int s16 = 0; s16 < 2; s16++) {
            uint32_t a[2][4];
            #pragma unroll
            for (int fm = 0; fm < 2; fm++) {
                int r = wm + fm * 16 + (lane & 15);
                uint32_t addr = s2u(Ab + r * APITCHB + (s16 * 2 + (lane >> 4)) * 16);
                ldsm_x4(a[fm], addr);
            }
            uint32_t b[8][2];
            #pragma unroll
            for (int fnp = 0; fnp < 4; fnp++) {
                int k = s16 * 16 + (lane & 7) + ((lane >> 3) & 1) * 8;
                int u = ((wn + fnp * 16) >> 3) + (lane >> 4);
                uint32_t r4[4];
                ldsm_x4_t(r4, s2u(Bb + k * 256 + ((u ^ (k & 7)) * 16)));
                b[2 * fnp][0] = r4[0]; b[2 * fnp][1] = r4[1];
                b[2 * fnp + 1][0] = r4[2]; b[2 * fnp + 1][1] = r4[3];
            }
            #pragma unroll
            for (int fm = 0; fm < 2; fm++)
                #pragma unroll
                for (int fn = 0; fn < 8; fn++)
                    mma_f16(c[fm][fn], a[fm], b[fn][0], b[fn][1]);
        }
        // no trailing barrier (see safety note above)
    }
    asm volatile("cp.async.wait_group 0;");
}

// ---------------------------------------------------------------- QKV GEMM (fp16)
__global__ __launch_bounds__(256, 2) void k_qkv_tc(
    int l, const float* __restrict__ bq, const float* __restrict__ bk_, const float* __restrict__ bv)
{
    extern __shared__ char smbuf[];
    const __half* Bg; const float* bias; __half* C;
    if (blockIdx.z == 0)      { Bg = g_Wqh + (size_t)l * H * H; bias = bq;  C = g_Qh; }
    else if (blockIdx.z == 1) { Bg = g_Wkh + (size_t)l * H * H; bias = bk_; C = g_Kh; }
    else                      { Bg = g_Wvh + (size_t)l * H * H; bias = bv;  C = g_Vh; }
    int m0 = blockIdx.y * 128, n0 = blockIdx.x * 128;
    const __half* Arow = g_H1h + (size_t)(m0 + (threadIdx.x >> 1)) * H;
    float c[2][8][4] = {};
    gemm_mainloop_h(Arow, 1, Bg, H, H, n0, c, smbuf);

    int lane = threadIdx.x & 31, warp = threadIdx.x >> 5;
    int grp = lane >> 2, qid = lane & 3;
    int wm = (warp & 3) * 32, wn = (warp >> 2) * 64;
    #pragma unroll
    for (int fn = 0; fn < 8; fn++) {
        int col = n0 + wn + fn * 8 + qid * 2;
        float bx = bias[col], by = bias[col + 1];
        #pragma unroll
        for (int fm = 0; fm < 2; fm++) {
            int m = m0 + wm + fm * 16 + grp;
            *(__half2*)&C[(size_t)m * H + col]       = __floats2half2_rn(c[fm][fn][0] + bx, c[fm][fn][1] + by);
            *(__half2*)&C[(size_t)(m + 8) * H + col] = __floats2half2_rn(c[fm][fn][2] + bx, c[fm][fn][3] + by);
        }
    }
}

// ---------------------------------------------------------------- FFN GEMM1 (gather + gelu, fp16)
__device__ __forceinline__ float gelu_f(float v) {
    return 0.5f * v * (1.0f + erff(v * 0.70710678118654752f));
}

__global__ __launch_bounds__(256, 2) void k_ffn1_tc(int l, const float* __restrict__ b1l)
{
    extern __shared__ char smbuf[];
    int e = blockIdx.z;
    int cnt = g_cnt[e];
    int m0 = blockIdx.y * 128;
    if (m0 >= cnt) return;
    int off = g_off[e];
    int n0 = blockIdx.x * 128;
    const __half* Bg = g_W1h + ((size_t)l * NE + e) * H * FF;
    const float* bias = b1l + (size_t)e * FF;

    int s = m0 + (threadIdx.x >> 1);
    int valid = (s < cnt);
    const __half* Arow = g_H1h + (size_t)(valid ? g_perm[off + s] : 0) * H;
    float c[2][8][4] = {};
    gemm_mainloop_h(Arow, valid, Bg, FF, H, n0, c, smbuf);

    int lane = threadIdx.x & 31, warp = threadIdx.x >> 5;
    int grp = lane >> 2, qid = lane & 3;
    int wm = (warp & 3) * 32, wn = (warp >> 2) * 64;
    #pragma unroll
    for (int fn = 0; fn < 8; fn++) {
        int col = n0 + wn + fn * 8 + qid * 2;
        float bx = bias[col], by = bias[col + 1];
        #pragma unroll
        for (int fm = 0; fm < 2; fm++) {
            int gm = m0 + wm + fm * 16 + grp;
            if (gm < cnt) {
                size_t r = (size_t)(off + gm) * FF + col;
                *(__half2*)&g_midh[r] = __floats2half2_rn(gelu_f(c[fm][fn][0] + bx), gelu_f(c[fm][fn][1] + by));
            }
            if (gm + 8 < cnt) {
                size_t r = (size_t)(off + gm + 8) * FF + col;
                *(__half2*)&g_midh[r] = __floats2half2_rn(gelu_f(c[fm][fn][2] + bx), gelu_f(c[fm][fn][3] + by));
            }
        }
    }
}

// ---------------------------------------------------------------- FFN GEMM2 (split-K=2, residual scatter)
constexpr int KSPLIT = 2;
constexpr int KCHUNK = FF / KSPLIT;   // 1536

__global__ __launch_bounds__(256, 2) void k_ffn2_tc(int l, const float* __restrict__ b2l,
                                                    float* __restrict__ x)
{
    extern __shared__ char smbuf[];
    int e = blockIdx.z >> 1;
    int ks = blockIdx.z & 1;
    int cnt = g_cnt[e];
    int m0 = blockIdx.y * 128;
    if (m0 >= cnt) return;
    int off = g_off[e];
    int n0 = blockIdx.x * 128;
    int kbase = ks * KCHUNK;
    const __half* Bg = g_W2h + ((size_t)l * NE + e) * FF * H + (size_t)kbase * H;
    const float* bias = b2l + (size_t)e * H;

    int s = m0 + (threadIdx.x >> 1);
    int valid = (s < cnt);
    const __half* Arow = g_midh + (size_t)(off + (valid ? s : m0)) * FF + kbase;
    float c[2][8][4] = {};
    gemm_mainloop_h(Arow, valid, Bg, H, KCHUNK, n0, c, smbuf);

    int lane = threadIdx.x & 31, warp = threadIdx.x >> 5;
    int grp = lane >> 2, qid = lane & 3;
    int wm = (warp & 3) * 32, wn = (warp >> 2) * 64;

    int tok0[2], tok1[2];
    #pragma unroll
    for (int fm = 0; fm < 2; fm++) {
        int gm = m0 + wm + fm * 16 + grp;
        tok0[fm] = (gm < cnt)     ? g_perm[off + gm]     : -1;
        tok1[fm] = (gm + 8 < cnt) ? g_perm[off + gm + 8] : -1;
    }
    #pragma unroll
    for (int fn = 0; fn < 8; fn++) {
        int col = n0 + wn + fn * 8 + qid * 2;
        float bx = (ks == 0) ? bias[col]     : 0.f;
        float by = (ks == 0) ? bias[col + 1] : 0.f;
        #pragma unroll
        for (int fm = 0; fm < 2; fm++) {
            if (tok0[fm] >= 0) {
                float* p = &x[(size_t)tok0[fm] * H + col];
                atomicAdd(p,     c[fm][fn][0] + bx);
                atomicAdd(p + 1, c[fm][fn][1] + by);
            }
            if (tok1[fm] >= 0) {
                float* p = &x[(size_t)tok1[fm] * H + col];
                atomicAdd(p,     c[fm][fn][2] + bx);
                atomicAdd(p + 1, c[fm][fn][3] + by);
            }
        }
    }
}

// ---------------------------------------------------------------- attention (fp16 mma, unchanged)
constexpr int ATTN_SMEM = 73728;

__global__ __launch_bounds__(128, 2) void k_attn_tc(float* __restrict__ x) {
    extern __shared__ char smc[];
    char* Qsh = smc;
    char* Ksh = smc + 8192;
    char* Vsh = smc + 40960;
    char* Psh = smc;
    int qt = blockIdx.x, hd = blockIdx.y, b = blockIdx.z;
    int tid = threadIdx.x;
    int lane = tid & 31, warp = tid >> 5;
    int grp = lane >> 2, qid = lane & 3;
    int hoff = hd * HD;
    int m = warp * 16;

    for (int cc = tid; cc < 64 * 8; cc += 128) {
        int r = cc >> 3, u = cc & 7;
        cp16(Qsh + r * 128 + ((u ^ (r & 7)) * 16),
             g_Qh + (size_t)(b * Sq + qt * 64 + r) * H + hoff + u * 8, 1);
    }
    for (int cc = tid; cc < 256 * 8; cc += 128) {
        int r = cc >> 3, u = cc & 7;
        cp16(Ksh + r * 128 + ((u ^ (r & 7)) * 16),
             g_Kh + (size_t)(b * Sq + r) * H + hoff + u * 8, 1);
        cp16(Vsh + r * 128 + ((u ^ (r & 7)) * 16),
             g_Vh + (size_t)(b * Sq + r) * H + hoff + u * 8, 1);
    }
    asm volatile("cp.async.commit_group;");
    asm volatile("cp.async.wait_group 0;");
    __syncthreads();

    float c[32][4];
    #pragma unroll
    for (int fn = 0; fn < 32; fn++)
        #pragma unroll
        for (int j = 0; j < 4; j++) c[fn][j] = 0.f;

    #pragma unroll
    for (int s = 0; s < 4; s++) {
        uint32_t a[4];
        {
            int r = m + (lane & 15);
            ldsm_x4(a, s2u(Qsh + r * 128 + (((s * 2 + (lane >> 4)) ^ (r & 7)) * 16)));
        }
        #pragma unroll
        for (int nb = 0; nb < 16; nb++) {
            int r = nb * 16 + (lane & 15);
            uint32_t bb[4];
            ldsm_x4(bb, s2u(Ksh + r * 128 + (((s * 2 + (lane >> 4)) ^ (r & 7)) * 16)));
            mma_f16(c[2 * nb],     a, bb[0], bb[2]);
            mma_f16(c[2 * nb + 1], a, bb[1], bb[3]);
        }
    }
    __syncthreads();

    float mx0 = -1e30f, mx1 = -1e30f;
    #pragma unroll
    for (int fn = 0; fn < 32; fn++) {
        mx0 = fmaxf(mx0, fmaxf(c[fn][0], c[fn][1]));
        mx1 = fmaxf(mx1, fmaxf(c[fn][2], c[fn][3]));
    }
    #pragma unroll
    for (int o = 1; o <= 2; o <<= 1) {
        mx0 = fmaxf(mx0, __shfl_xor_sync(0xffffffffu, mx0, o));
        mx1 = fmaxf(mx1, __shfl_xor_sync(0xffffffffu, mx1, o));
    }
    float s0 = 0.f, s1 = 0.f;
    #pragma unroll
    for (int fn = 0; fn < 32; fn++) {
        c[fn][0] = __expf(c[fn][0] - mx0); s0 += c[fn][0];
        c[fn][1] = __expf(c[fn][1] - mx0); s0 += c[fn][1];
        c[fn][2] = __expf(c[fn][2] - mx1); s1 += c[fn][2];
        c[fn][3] = __expf(c[fn][3] - mx1); s1 += c[fn][3];
    }
    #pragma unroll
    for (int o = 1; o <= 2; o <<= 1) {
        s0 += __shfl_xor_sync(0xffffffffu, s0, o);
        s1 += __shfl_xor_sync(0xffffffffu, s1, o);
    }
    float inv0 = 1.f / s0, inv1 = 1.f / s1;
    #pragma unroll
    for (int fn = 0; fn < 32; fn++) {
        int r0 = m + grp, r1 = r0 + 8;
        int u0 = fn ^ (r0 & 7), u1 = fn ^ (r1 & 7);
        *(__half2*)(Psh + r0 * 512 + u0 * 16 + qid * 4) = __floats2half2_rn(c[fn][0] * inv0, c[fn][1] * inv0);
        *(__half2*)(Psh + r1 * 512 + u1 * 16 + qid * 4) = __floats2half2_rn(c[fn][2] * inv1, c[fn][3] * inv1);
    }
    __syncwarp();

    float c2[8][4];
    #pragma unroll
    for (int fn = 0; fn < 8; fn++)
        #pragma unroll
        for (int j = 0; j < 4; j++) c2[fn][j] = 0.f;

    #pragma unroll 4
    for (int s = 0; s < 16; s++) {
        uint32_t a[4];
        {
            int r = m + (lane & 15);
            int u = s * 2 + (lane >> 4);
            ldsm_x4(a, s2u(Psh + r * 512 + ((u ^ (r & 7)) * 16)));
        }
        #pragma unroll
        for (int nb = 0; nb < 4; nb++) {
            int k = s * 16 + (lane & 7) + ((lane >> 3) & 1) * 8;
            int u = nb * 2 + (lane >> 4);
            uint32_t r4[4];
            ldsm_x4_t(r4, s2u(Vsh + k * 128 + ((u ^ (k & 7)) * 16)));
            mma_f16(c2[2 * nb],     a, r4[0], r4[1]);
            mma_f16(c2[2 * nb + 1], a, r4[2], r4[3]);
        }
    }

    #pragma unroll
    for (int fn = 0; fn < 8; fn++) {
        int col = hoff + fn * 8 + qid * 2;
        size_t r0 = (size_t)(b * Sq + qt * 64 + m + grp) * H + col;
        size_t r1 = r0 + (size_t)8 * H;
        float2 v0 = *(float2*)&x[r0];
        v0.x += c2[fn][0]; v0.y += c2[fn][1];
        *(float2*)&x[r0] = v0;
        float2 v1 = *(float2*)&x[r1];
        v1.x += c2[fn][2]; v1.y += c2[fn][3];
        *(float2*)&x[r1] = v1;
    }
}

// ---------------------------------------------------------------- launch
extern "C" void kernel_launch(void* const* d_in, const int* in_sizes, int n_in,
                              void* d_out, int out_size) {
    (void)in_sizes; (void)n_in; (void)out_size;
    const float* x_in  = (const float*)d_in[0];
    const int*   ntp   = (const int*)d_in[2];
    const float* Wq    = (const float*)d_in[3];
    const float* bq    = (const float*)d_in[4];
    const float* Wk    = (const float*)d_in[5];
    const float* bk    = (const float*)d_in[6];
    const float* Wv    = (const float*)d_in[7];
    const float* bv    = (const float*)d_in[8];
    const float* ln1w  = (const float*)d_in[9];
    const float* ln1b  = (const float*)d_in[10];
    const float* ln2w  = (const float*)d_in[11];
    const float* ln2b  = (const float*)d_in[12];
    const float* W1    = (const float*)d_in[13];
    const float* b1    = (const float*)d_in[14];
    const float* W2    = (const float*)d_in[15];
    const float* b2    = (const float*)d_in[16];
    float* x = (float*)d_out;

    cudaFuncSetAttribute(k_attn_tc, cudaFuncAttributeMaxDynamicSharedMemorySize, ATTN_SMEM);
    cudaFuncSetAttribute(k_qkv_tc,  cudaFuncAttributeMaxDynamicSharedMemorySize, GEMM_SMEM);
    cudaFuncSetAttribute(k_ffn1_tc, cudaFuncAttributeMaxDynamicSharedMemorySize, GEMM_SMEM);
    cudaFuncSetAttribute(k_ffn2_tc, cudaFuncAttributeMaxDynamicSharedMemorySize, GEMM_SMEM);

    __half* dWq; cudaGetSymbolAddress((void**)&dWq, g_Wqh);
    __half* dWk; cudaGetSymbolAddress((void**)&dWk, g_Wkh);
    __half* dWv; cudaGetSymbolAddress((void**)&dWv, g_Wvh);
    __half* dW1; cudaGetSymbolAddress((void**)&dW1, g_W1h);
    __half* dW2; cudaGetSymbolAddress((void**)&dW2, g_W2h);
    int nqkv = Lr * H * H;
    int nff  = Lr * NE * H * FF;

    k_f2h<<<(nqkv / 4 + 255) / 256, 256>>>(Wq, dWq, nqkv);
    k_f2h<<<(nqkv / 4 + 255) / 256, 256>>>(Wk, dWk, nqkv);
    k_f2h<<<(nqkv / 4 + 255) / 256, 256>>>(Wv, dWv, nqkv);
    k_route<<<1, 1024>>>(ntp);
    k_pe_ln<<<T, 256>>>(x_in, x, ln1w, ln1b);
    k_qkv_tc<<<dim3(H / 128, T / 128, 3), 256, GEMM_SMEM>>>(0, bq, bk, bv);

    k_f2h<<<(nff / 4 + 255) / 256, 256>>>(W1, dW1, nff);
    k_f2h<<<(nff / 4 + 255) / 256, 256>>>(W2, dW2, nff);

    k_attn_tc<<<dim3(Sq / 64, NH, Bz), 128, ATTN_SMEM>>>(x);
    k_ln<<<T, 256>>>(x, ln2w, ln2b);
    k_ffn1_tc<<<dim3(FF / 128, T / 128, NE), 256, GEMM_SMEM>>>(0, b1);
    k_ffn2_tc<<<dim3(H / 128, T / 128, NE * KSPLIT), 256, GEMM_SMEM>>>(0, b2, x);

    // layer 1
    k_ln<<<T, 256>>>(x, ln1w + H, ln1b + H);
    k_qkv_tc<<<dim3(H / 128, T / 128, 3), 256, GEMM_SMEM>>>(
        1, bq + H, bk + H, bv + H);
    k_attn_tc<<<dim3(Sq / 64, NH, Bz), 128, ATTN_SMEM>>>(x);
    k_ln<<<T, 256>>>(x, ln2w + H, ln2b + H);
    k_ffn1_tc<<<dim3(FF / 128, T / 128, NE), 256, GEMM_SMEM>>>(1, b1 + (size_t)NE * FF);
    k_ffn2_tc<<<dim3(H / 128, T / 128, NE * KSPLIT), 256, GEMM_SMEM>>>(1, b2 + (size_t)NE * H, x);
}